// round 1
// baseline (speedup 1.0000x reference)
#include <cuda_runtime.h>
#include <math.h>

// Problem dims
#define S_   128
#define R_   256
#define CM_  256
#define CZ_  128
#define NH_  8
#define CH_  32
#define HC_  256          // NH_*CH_
#define MTOT (S_*R_)      // 32768

// ---------------- scratch (static __device__, no allocations) ----------------
__device__ float g_mln[MTOT*CM_];         // LN(m)            32 MB
__device__ float g_q[MTOT*HC_];           // [s,h,r,c]        32 MB
__device__ float g_k[MTOT*HC_];
__device__ float g_v[MTOT*HC_];
__device__ float g_g[MTOT*HC_];
__device__ float g_og[MTOT*HC_];          // (o*g), [m, h*32+c]
__device__ float g_zb[NH_*R_*R_];         // pair bias [h,i,j]  2 MB

// ---------------- kernel 1: LayerNorm(m) ----------------
// warp per row of 256; grid = MTOT/8 blocks x 256 threads
__global__ __launch_bounds__(256) void ln_m_kernel(const float* __restrict__ m,
                                                   const float* __restrict__ g,
                                                   const float* __restrict__ b) {
    int warp = threadIdx.x >> 5, lane = threadIdx.x & 31;
    int row = blockIdx.x * 8 + warp;
    const float* x = m + (size_t)row * CM_;
    float4 a = *(const float4*)(x + lane * 4);
    float4 c = *(const float4*)(x + 128 + lane * 4);
    float s  = a.x + a.y + a.z + a.w + c.x + c.y + c.z + c.w;
    float ss = a.x*a.x + a.y*a.y + a.z*a.z + a.w*a.w
             + c.x*c.x + c.y*c.y + c.z*c.z + c.w*c.w;
    #pragma unroll
    for (int o = 16; o > 0; o >>= 1) {
        s  += __shfl_xor_sync(0xffffffffu, s,  o);
        ss += __shfl_xor_sync(0xffffffffu, ss, o);
    }
    float mu   = s * (1.0f / CM_);
    float var  = ss * (1.0f / CM_) - mu * mu;
    float rstd = rsqrtf(var + 1e-5f);
    float* y = g_mln + (size_t)row * CM_;
    {
        float4 gg = *(const float4*)(g + lane * 4);
        float4 bb = *(const float4*)(b + lane * 4);
        float4 r;
        r.x = (a.x - mu) * rstd * gg.x + bb.x;
        r.y = (a.y - mu) * rstd * gg.y + bb.y;
        r.z = (a.z - mu) * rstd * gg.z + bb.z;
        r.w = (a.w - mu) * rstd * gg.w + bb.w;
        *(float4*)(y + lane * 4) = r;
    }
    {
        float4 gg = *(const float4*)(g + 128 + lane * 4);
        float4 bb = *(const float4*)(b + 128 + lane * 4);
        float4 r;
        r.x = (c.x - mu) * rstd * gg.x + bb.x;
        r.y = (c.y - mu) * rstd * gg.y + bb.y;
        r.z = (c.z - mu) * rstd * gg.z + bb.z;
        r.w = (c.w - mu) * rstd * gg.w + bb.w;
        *(float4*)(y + 128 + lane * 4) = r;
    }
}

// ---------------- kernel 2: pair bias zb[h,i,j] = LN(z)[i,j,:] @ w_z[:,h] ----------------
// warp per z-row (128 elems); grid = R_*R_/8 blocks x 256 threads
__global__ __launch_bounds__(256) void zbias_kernel(const float* __restrict__ z,
                                                    const float* __restrict__ gz,
                                                    const float* __restrict__ bz,
                                                    const float* __restrict__ wz) {
    __shared__ float wsT[NH_ * CZ_];   // transposed: wsT[h*128 + e] = wz[e*8 + h]
    int tid = threadIdx.x;
    for (int i = tid; i < NH_ * CZ_; i += 256) {
        int h = i / CZ_, e = i % CZ_;
        wsT[i] = wz[e * NH_ + h];
    }
    __syncthreads();
    int warp = tid >> 5, lane = tid & 31;
    int p = blockIdx.x * 8 + warp;                 // (i,j) flattened
    const float* x = z + (size_t)p * CZ_;
    float4 a = *(const float4*)(x + lane * 4);
    float s  = a.x + a.y + a.z + a.w;
    float ss = a.x*a.x + a.y*a.y + a.z*a.z + a.w*a.w;
    #pragma unroll
    for (int o = 16; o > 0; o >>= 1) {
        s  += __shfl_xor_sync(0xffffffffu, s,  o);
        ss += __shfl_xor_sync(0xffffffffu, ss, o);
    }
    float mu   = s * (1.0f / CZ_);
    float var  = ss * (1.0f / CZ_) - mu * mu;
    float rstd = rsqrtf(var + 1e-5f);
    int col = lane * 4;
    float4 gg = *(const float4*)(gz + col);
    float4 bb = *(const float4*)(bz + col);
    float n0 = (a.x - mu) * rstd * gg.x + bb.x;
    float n1 = (a.y - mu) * rstd * gg.y + bb.y;
    float n2 = (a.z - mu) * rstd * gg.z + bb.z;
    float n3 = (a.w - mu) * rstd * gg.w + bb.w;
    float keep = 0.0f;
    #pragma unroll
    for (int h = 0; h < NH_; h++) {
        float4 w = *(const float4*)(&wsT[h * CZ_ + col]);
        float part = n0 * w.x + n1 * w.y + n2 * w.z + n3 * w.w;
        #pragma unroll
        for (int o = 16; o > 0; o >>= 1)
            part += __shfl_xor_sync(0xffffffffu, part, o);
        if (lane == h) keep = part;
    }
    if (lane < NH_) g_zb[(size_t)lane * R_ * R_ + p] = keep;
}

// ---------------- kernel 3: projections  [32768,256] @ [256, 4*256] ----------------
// 128x128 tile, 256 threads, 8x8 microtile, K-tile 8, register prefetch.
// blockIdx.y in [0,8): mat = y>>1 (q,k,v,g), col offset (y&1)*128
__global__ __launch_bounds__(256) void sgemm_proj(const float* __restrict__ wq,
                                                  const float* __restrict__ wk,
                                                  const float* __restrict__ wv,
                                                  const float* __restrict__ wg,
                                                  const float* __restrict__ bg) {
    __shared__ float As[8][128];
    __shared__ float Bs[8][128];
    int m0    = blockIdx.x * 128;
    int by    = blockIdx.y;
    int mat   = by >> 1;
    int coln0 = (by & 1) * 128;
    const float* W = (mat == 0) ? wq : (mat == 1) ? wk : (mat == 2) ? wv : wg;

    int tid  = threadIdx.x;
    int arow = tid >> 1, acol = (tid & 1) << 2;
    int brow = tid >> 5, bcol = (tid & 31) << 2;
    const float* Ap = g_mln + (size_t)(m0 + arow) * CM_ + acol;
    const float* Bp = W + (size_t)brow * HC_ + coln0 + bcol;
    int tx = tid & 15, ty = tid >> 4;
    int ty8 = ty * 8, tx8 = tx * 8;

    float acc[8][8];
    #pragma unroll
    for (int i = 0; i < 8; i++)
        #pragma unroll
        for (int j = 0; j < 8; j++) acc[i][j] = 0.0f;

    float4 a4 = *(const float4*)Ap;
    float4 b4 = *(const float4*)Bp;

    for (int k0 = 0; k0 < CM_; k0 += 8) {
        As[acol + 0][arow] = a4.x;
        As[acol + 1][arow] = a4.y;
        As[acol + 2][arow] = a4.z;
        As[acol + 3][arow] = a4.w;
        *(float4*)&Bs[brow][bcol] = b4;
        __syncthreads();
        if (k0 + 8 < CM_) {
            a4 = *(const float4*)(Ap + k0 + 8);
            b4 = *(const float4*)(Bp + (size_t)(k0 + 8) * HC_);
        }
        #pragma unroll
        for (int kk = 0; kk < 8; kk++) {
            float4 t0 = *(const float4*)(&As[kk][ty8]);
            float4 t1 = *(const float4*)(&As[kk][ty8 + 4]);
            float4 t2 = *(const float4*)(&Bs[kk][tx8]);
            float4 t3 = *(const float4*)(&Bs[kk][tx8 + 4]);
            float ra[8] = {t0.x, t0.y, t0.z, t0.w, t1.x, t1.y, t1.z, t1.w};
            float rb[8] = {t2.x, t2.y, t2.z, t2.w, t3.x, t3.y, t3.z, t3.w};
            #pragma unroll
            for (int i = 0; i < 8; i++)
                #pragma unroll
                for (int j = 0; j < 8; j++)
                    acc[i][j] = fmaf(ra[i], rb[j], acc[i][j]);
        }
        __syncthreads();
    }

    const float qscale = 0.17677669529663687f;   // 1/sqrt(32)
    #pragma unroll
    for (int i = 0; i < 8; i++) {
        int mrow = m0 + ty8 + i;
        int s  = mrow >> 8, rr = mrow & 255;
        #pragma unroll
        for (int j = 0; j < 8; j += 4) {
            int coln = coln0 + tx8 + j;
            int h = coln >> 5, c = coln & 31;
            size_t dst = (((size_t)(s * NH_ + h) * R_ + rr) * CH_ + c);
            float4 o;
            if (mat == 0) {
                o.x = acc[i][j]   * qscale; o.y = acc[i][j+1] * qscale;
                o.z = acc[i][j+2] * qscale; o.w = acc[i][j+3] * qscale;
                *(float4*)(g_q + dst) = o;
            } else if (mat == 1) {
                o.x = acc[i][j]; o.y = acc[i][j+1]; o.z = acc[i][j+2]; o.w = acc[i][j+3];
                *(float4*)(g_k + dst) = o;
            } else if (mat == 2) {
                o.x = acc[i][j]; o.y = acc[i][j+1]; o.z = acc[i][j+2]; o.w = acc[i][j+3];
                *(float4*)(g_v + dst) = o;
            } else {
                o.x = 1.0f / (1.0f + __expf(-(acc[i][j]   + bg[coln])));
                o.y = 1.0f / (1.0f + __expf(-(acc[i][j+1] + bg[coln+1])));
                o.z = 1.0f / (1.0f + __expf(-(acc[i][j+2] + bg[coln+2])));
                o.w = 1.0f / (1.0f + __expf(-(acc[i][j+3] + bg[coln+3])));
                *(float4*)(g_g + dst) = o;
            }
        }
    }
}

// ---------------- kernel 4: fused attention per (s,h) ----------------
// Block = 256 threads, one query row per thread, K/V resident in SMEM,
// tile-wise online softmax (16 keys/tile), zb tile staged in SMEM (pad 17).
#define KT 16
__global__ __launch_bounds__(256) void attn_kernel(const float* __restrict__ mask) {
    extern __shared__ float sm[];
    float* ksm = sm;                      // 256*32
    float* vsm = ksm + R_ * CH_;          // 256*32
    float* zbs = vsm + R_ * CH_;          // 256*17
    float* mb  = zbs + R_ * 17;           // 256

    int sh = blockIdx.x;
    int s = sh >> 3, h = sh & 7;
    int t = threadIdx.x;

    const float4* kp = (const float4*)(g_k + (size_t)sh * R_ * CH_);
    const float4* vp = (const float4*)(g_v + (size_t)sh * R_ * CH_);
    float4* ks4 = (float4*)ksm;
    float4* vs4 = (float4*)vsm;
    #pragma unroll
    for (int i = t; i < R_ * CH_ / 4; i += 256) { ks4[i] = kp[i]; vs4[i] = vp[i]; }
    mb[t] = 1e9f * (mask[s * R_ + t] - 1.0f);

    float4 q4[8];
    const float4* qp = (const float4*)(g_q + ((size_t)sh * R_ + t) * CH_);
    #pragma unroll
    for (int j = 0; j < 8; j++) q4[j] = qp[j];
    __syncthreads();

    float mmax = -1e30f, lsum = 0.0f;
    float o[32];
    #pragma unroll
    for (int c = 0; c < 32; c++) o[c] = 0.0f;

    const float* zrow = g_zb + (size_t)h * R_ * R_;

    for (int k0 = 0; k0 < R_; k0 += KT) {
        __syncthreads();
        // stage zb[h][q][k0..k0+15] for all 256 q (coalesced gmem, padded smem)
        for (int i = t; i < R_ * KT / 4; i += 256) {
            int q_ = i >> 2, kq = (i & 3) << 2;
            float4 f = *(const float4*)(zrow + (size_t)q_ * R_ + k0 + kq);
            float* d = zbs + q_ * 17 + kq;
            d[0] = f.x; d[1] = f.y; d[2] = f.z; d[3] = f.w;
        }
        __syncthreads();

        float lg[KT];
        #pragma unroll
        for (int kk = 0; kk < KT; kk++) {
            int k = k0 + kk;
            const float4* kr = (const float4*)(ksm + (k << 5));
            float d0 = 0.0f, d1 = 0.0f;
            #pragma unroll
            for (int j = 0; j < 8; j += 2) {
                float4 kv0 = kr[j];
                float4 kv1 = kr[j + 1];
                d0 = fmaf(q4[j].x, kv0.x, d0); d0 = fmaf(q4[j].y, kv0.y, d0);
                d0 = fmaf(q4[j].z, kv0.z, d0); d0 = fmaf(q4[j].w, kv0.w, d0);
                d1 = fmaf(q4[j+1].x, kv1.x, d1); d1 = fmaf(q4[j+1].y, kv1.y, d1);
                d1 = fmaf(q4[j+1].z, kv1.z, d1); d1 = fmaf(q4[j+1].w, kv1.w, d1);
            }
            lg[kk] = d0 + d1 + mb[k] + zbs[t * 17 + kk];
        }
        float tmax = lg[0];
        #pragma unroll
        for (int kk = 1; kk < KT; kk++) tmax = fmaxf(tmax, lg[kk]);
        float newm = fmaxf(mmax, tmax);
        float corr = __expf(mmax - newm);
        mmax = newm;
        lsum *= corr;
        #pragma unroll
        for (int c = 0; c < 32; c++) o[c] *= corr;
        #pragma unroll
        for (int kk = 0; kk < KT; kk++) {
            float p = __expf(lg[kk] - mmax);
            lsum += p;
            const float4* vr = (const float4*)(vsm + ((k0 + kk) << 5));
            #pragma unroll
            for (int j = 0; j < 8; j++) {
                float4 vv = vr[j];
                o[4*j+0] = fmaf(p, vv.x, o[4*j+0]);
                o[4*j+1] = fmaf(p, vv.y, o[4*j+1]);
                o[4*j+2] = fmaf(p, vv.z, o[4*j+2]);
                o[4*j+3] = fmaf(p, vv.w, o[4*j+3]);
            }
        }
    }

    float inv = 1.0f / lsum;
    const float4* gp = (const float4*)(g_g + ((size_t)sh * R_ + t) * CH_);
    float4* op = (float4*)(g_og + ((size_t)(s * R_ + t)) * HC_ + h * CH_);
    #pragma unroll
    for (int j = 0; j < 8; j++) {
        float4 gg = gp[j];
        float4 r;
        r.x = o[4*j+0] * inv * gg.x;
        r.y = o[4*j+1] * inv * gg.y;
        r.z = o[4*j+2] * inv * gg.z;
        r.w = o[4*j+3] * inv * gg.w;
        op[j] = r;
    }
}

// ---------------- kernel 5: output GEMM  out = og @ wo + bo ----------------
__global__ __launch_bounds__(256) void sgemm_out(const float* __restrict__ wo,
                                                 const float* __restrict__ bo,
                                                 float* __restrict__ out) {
    __shared__ float As[8][128];
    __shared__ float Bs[8][128];
    int m0    = blockIdx.x * 128;
    int coln0 = blockIdx.y * 128;

    int tid  = threadIdx.x;
    int arow = tid >> 1, acol = (tid & 1) << 2;
    int brow = tid >> 5, bcol = (tid & 31) << 2;
    const float* Ap = g_og + (size_t)(m0 + arow) * HC_ + acol;
    const float* Bp = wo + (size_t)brow * CM_ + coln0 + bcol;
    int tx = tid & 15, ty = tid >> 4;
    int ty8 = ty * 8, tx8 = tx * 8;

    float acc[8][8];
    #pragma unroll
    for (int i = 0; i < 8; i++)
        #pragma unroll
        for (int j = 0; j < 8; j++) acc[i][j] = 0.0f;

    float4 a4 = *(const float4*)Ap;
    float4 b4 = *(const float4*)Bp;

    for (int k0 = 0; k0 < HC_; k0 += 8) {
        As[acol + 0][arow] = a4.x;
        As[acol + 1][arow] = a4.y;
        As[acol + 2][arow] = a4.z;
        As[acol + 3][arow] = a4.w;
        *(float4*)&Bs[brow][bcol] = b4;
        __syncthreads();
        if (k0 + 8 < HC_) {
            a4 = *(const float4*)(Ap + k0 + 8);
            b4 = *(const float4*)(Bp + (size_t)(k0 + 8) * CM_);
        }
        #pragma unroll
        for (int kk = 0; kk < 8; kk++) {
            float4 t0 = *(const float4*)(&As[kk][ty8]);
            float4 t1 = *(const float4*)(&As[kk][ty8 + 4]);
            float4 t2 = *(const float4*)(&Bs[kk][tx8]);
            float4 t3 = *(const float4*)(&Bs[kk][tx8 + 4]);
            float ra[8] = {t0.x, t0.y, t0.z, t0.w, t1.x, t1.y, t1.z, t1.w};
            float rb[8] = {t2.x, t2.y, t2.z, t2.w, t3.x, t3.y, t3.z, t3.w};
            #pragma unroll
            for (int i = 0; i < 8; i++)
                #pragma unroll
                for (int j = 0; j < 8; j++)
                    acc[i][j] = fmaf(ra[i], rb[j], acc[i][j]);
        }
        __syncthreads();
    }

    #pragma unroll
    for (int i = 0; i < 8; i++) {
        int mrow = m0 + ty8 + i;
        #pragma unroll
        for (int j = 0; j < 8; j += 4) {
            int coln = coln0 + tx8 + j;
            float4 bb = *(const float4*)(bo + coln);
            float4 o;
            o.x = acc[i][j]   + bb.x;
            o.y = acc[i][j+1] + bb.y;
            o.z = acc[i][j+2] + bb.z;
            o.w = acc[i][j+3] + bb.w;
            *(float4*)(out + (size_t)mrow * CM_ + coln) = o;
        }
    }
}

// ---------------- launch ----------------
extern "C" void kernel_launch(void* const* d_in, const int* in_sizes, int n_in,
                              void* d_out, int out_size) {
    (void)in_sizes; (void)n_in; (void)out_size;
    const float* m      = (const float*)d_in[0];
    const float* z      = (const float*)d_in[1];
    const float* mask   = (const float*)d_in[2];
    const float* ln_m_g = (const float*)d_in[3];
    const float* ln_m_b = (const float*)d_in[4];
    const float* ln_z_g = (const float*)d_in[5];
    const float* ln_z_b = (const float*)d_in[6];
    const float* w_z    = (const float*)d_in[7];
    const float* wq     = (const float*)d_in[8];
    const float* wk     = (const float*)d_in[9];
    const float* wv     = (const float*)d_in[10];
    const float* wg     = (const float*)d_in[11];
    const float* bg     = (const float*)d_in[12];
    const float* wo     = (const float*)d_in[13];
    const float* bo     = (const float*)d_in[14];
    float* out = (float*)d_out;

    ln_m_kernel<<<MTOT / 8, 256>>>(m, ln_m_g, ln_m_b);
    zbias_kernel<<<R_ * R_ / 8, 256>>>(z, ln_z_g, ln_z_b, w_z);
    sgemm_proj<<<dim3(MTOT / 128, 8), 256>>>(wq, wk, wv, wg, bg);

    const int attn_smem = (R_ * CH_ * 2 + R_ * 17 + R_) * (int)sizeof(float); // 83968 B
    cudaFuncSetAttribute(attn_kernel, cudaFuncAttributeMaxDynamicSharedMemorySize, attn_smem);
    attn_kernel<<<S_ * NH_, 256, attn_smem>>>(mask);

    sgemm_out<<<dim3(MTOT / 128, 2), 256>>>(wo, bo, out);
}

// round 6
// speedup vs baseline: 1.5860x; 1.5860x over previous
#include <cuda_runtime.h>
#include <math.h>
#include <stdint.h>

#define S_   128
#define R_   256
#define CM_  256
#define CZ_  128
#define NH_  8
#define CH_  32
#define HC_  256
#define MTOT (S_*R_)

// ---------------- scratch ----------------
__device__ float g_mln[MTOT*CM_];            // LN(m), tf32-rounded   [m][k]
__device__ float g_q[NH_*S_*R_*CH_];         // [s*8+h][r][c]
__device__ float g_k[NH_*S_*R_*CH_];
__device__ float g_v[NH_*S_*R_*CH_];
__device__ float g_g[NH_*S_*R_*CH_];
__device__ float g_og[MTOT*HC_];             // (o*g), tf32-rounded   [m][hc]
__device__ float g_zb[NH_*R_*R_];            // pair bias [h][q][k]
__device__ float g_wT[4*HC_*CM_];            // [mat*256+n][k], tf32-rounded
__device__ float g_woT[CM_*HC_];             // [n][k], tf32-rounded

static __device__ __forceinline__ float rtf32(float x) {
    uint32_t u; asm("cvt.rn.tf32.f32 %0, %1;" : "=r"(u) : "f"(x));
    return __uint_as_float(u);
}
static __device__ __forceinline__ void mma16n8k8(float* d, const uint32_t* a, const uint32_t* b) {
    asm volatile("mma.sync.aligned.m16n8k8.row.col.f32.tf32.tf32.f32 "
        "{%0,%1,%2,%3}, {%4,%5,%6,%7}, {%8,%9}, {%0,%1,%2,%3};"
        : "+f"(d[0]), "+f"(d[1]), "+f"(d[2]), "+f"(d[3])
        : "r"(a[0]), "r"(a[1]), "r"(a[2]), "r"(a[3]), "r"(b[0]), "r"(b[1]));
}

// ---------------- kernel 1: LayerNorm(m) -> tf32-rounded ----------------
__global__ __launch_bounds__(256) void ln_m_kernel(const float* __restrict__ m,
                                                   const float* __restrict__ g,
                                                   const float* __restrict__ b) {
    int warp = threadIdx.x >> 5, lane = threadIdx.x & 31;
    int row = blockIdx.x * 8 + warp;
    const float* x = m + (size_t)row * CM_;
    float4 a = *(const float4*)(x + lane * 4);
    float4 c = *(const float4*)(x + 128 + lane * 4);
    float s  = a.x + a.y + a.z + a.w + c.x + c.y + c.z + c.w;
    float ss = a.x*a.x + a.y*a.y + a.z*a.z + a.w*a.w
             + c.x*c.x + c.y*c.y + c.z*c.z + c.w*c.w;
    #pragma unroll
    for (int o = 16; o > 0; o >>= 1) {
        s  += __shfl_xor_sync(0xffffffffu, s,  o);
        ss += __shfl_xor_sync(0xffffffffu, ss, o);
    }
    float mu   = s * (1.0f / CM_);
    float var  = ss * (1.0f / CM_) - mu * mu;
    float rstd = rsqrtf(var + 1e-5f);
    float* y = g_mln + (size_t)row * CM_;
    {
        float4 gg = *(const float4*)(g + lane * 4);
        float4 bb = *(const float4*)(b + lane * 4);
        float4 r;
        r.x = rtf32((a.x - mu) * rstd * gg.x + bb.x);
        r.y = rtf32((a.y - mu) * rstd * gg.y + bb.y);
        r.z = rtf32((a.z - mu) * rstd * gg.z + bb.z);
        r.w = rtf32((a.w - mu) * rstd * gg.w + bb.w);
        *(float4*)(y + lane * 4) = r;
    }
    {
        float4 gg = *(const float4*)(g + 128 + lane * 4);
        float4 bb = *(const float4*)(b + 128 + lane * 4);
        float4 r;
        r.x = rtf32((c.x - mu) * rstd * gg.x + bb.x);
        r.y = rtf32((c.y - mu) * rstd * gg.y + bb.y);
        r.z = rtf32((c.z - mu) * rstd * gg.z + bb.z);
        r.w = rtf32((c.w - mu) * rstd * gg.w + bb.w);
        *(float4*)(y + 128 + lane * 4) = r;
    }
}

// ---------------- kernel 2: pair bias ----------------
__global__ __launch_bounds__(256) void zbias_kernel(const float* __restrict__ z,
                                                    const float* __restrict__ gz,
                                                    const float* __restrict__ bz,
                                                    const float* __restrict__ wz) {
    __shared__ float wsT[NH_ * CZ_];
    int tid = threadIdx.x;
    for (int i = tid; i < NH_ * CZ_; i += 256) {
        int h = i / CZ_, e = i % CZ_;
        wsT[i] = wz[e * NH_ + h];
    }
    __syncthreads();
    int warp = tid >> 5, lane = tid & 31;
    int p = blockIdx.x * 8 + warp;
    const float* x = z + (size_t)p * CZ_;
    float4 a = *(const float4*)(x + lane * 4);
    float s  = a.x + a.y + a.z + a.w;
    float ss = a.x*a.x + a.y*a.y + a.z*a.z + a.w*a.w;
    #pragma unroll
    for (int o = 16; o > 0; o >>= 1) {
        s  += __shfl_xor_sync(0xffffffffu, s,  o);
        ss += __shfl_xor_sync(0xffffffffu, ss, o);
    }
    float mu   = s * (1.0f / CZ_);
    float var  = ss * (1.0f / CZ_) - mu * mu;
    float rstd = rsqrtf(var + 1e-5f);
    int col = lane * 4;
    float4 gg = *(const float4*)(gz + col);
    float4 bb = *(const float4*)(bz + col);
    float n0 = (a.x - mu) * rstd * gg.x + bb.x;
    float n1 = (a.y - mu) * rstd * gg.y + bb.y;
    float n2 = (a.z - mu) * rstd * gg.z + bb.z;
    float n3 = (a.w - mu) * rstd * gg.w + bb.w;
    float keep = 0.0f;
    #pragma unroll
    for (int h = 0; h < NH_; h++) {
        float4 w = *(const float4*)(&wsT[h * CZ_ + col]);
        float part = n0 * w.x + n1 * w.y + n2 * w.z + n3 * w.w;
        #pragma unroll
        for (int o = 16; o > 0; o >>= 1)
            part += __shfl_xor_sync(0xffffffffu, part, o);
        if (lane == h) keep = part;
    }
    if (lane < NH_) g_zb[(size_t)lane * R_ * R_ + p] = keep;
}

// ---------------- kernel 2b: weight transpose + tf32 round ----------------
__global__ __launch_bounds__(256) void wtrans_kernel(const float* __restrict__ wq,
                                                     const float* __restrict__ wk,
                                                     const float* __restrict__ wv,
                                                     const float* __restrict__ wg,
                                                     const float* __restrict__ wo) {
    __shared__ float t[32][33];
    int mat = blockIdx.z;
    const float* W = (mat == 0) ? wq : (mat == 1) ? wk : (mat == 2) ? wv : (mat == 3) ? wg : wo;
    float* D = (mat < 4) ? (g_wT + (size_t)mat * HC_ * CM_) : g_woT;
    int bx = blockIdx.x, by = blockIdx.y;
    int tx = threadIdx.x & 31, ty8 = threadIdx.x >> 5;
    #pragma unroll
    for (int r = 0; r < 32; r += 8)
        t[ty8 + r][tx] = W[(size_t)(by * 32 + ty8 + r) * 256 + bx * 32 + tx];
    __syncthreads();
    #pragma unroll
    for (int r = 0; r < 32; r += 8)
        D[(size_t)(bx * 32 + ty8 + r) * 256 + by * 32 + tx] = rtf32(t[tx][ty8 + r]);
}

// ---------------- warp-mma tf32 mainloop: 128x128 tile, K=256 ----------------
// 8 warps, each 64x32 via 4x4 m16n8k8. As/Bs: [128][36] (rows: m / n), conflict-free.
static __device__ __forceinline__ void wm_mainloop(const float* __restrict__ Arow0,
                                                   const float* __restrict__ Brow0,
                                                   float* As, float* Bs,
                                                   float acc[4][4][4]) {
    int tid = threadIdx.x;
    int wid = tid >> 5, lane = tid & 31;
    int g = lane >> 2, t = lane & 3;
    int wm = (wid >> 2) * 64, wn = (wid & 3) * 32;
    int lrow = tid >> 1, lk = (tid & 1) * 16;
    #pragma unroll 1
    for (int k0 = 0; k0 < 256; k0 += 32) {
        __syncthreads();
        #pragma unroll
        for (int j = 0; j < 16; j += 4) {
            *(float4*)(As + lrow * 36 + lk + j) =
                *(const float4*)(Arow0 + (size_t)lrow * 256 + k0 + lk + j);
            *(float4*)(Bs + lrow * 36 + lk + j) =
                *(const float4*)(Brow0 + (size_t)lrow * 256 + k0 + lk + j);
        }
        __syncthreads();
        #pragma unroll
        for (int kk = 0; kk < 32; kk += 8) {
            uint32_t af[4][4], bf[4][2];
            #pragma unroll
            for (int mi = 0; mi < 4; mi++) {
                const float* ap = As + (wm + mi * 16 + g) * 36 + kk + t;
                af[mi][0] = __float_as_uint(ap[0]);
                af[mi][1] = __float_as_uint(ap[8 * 36]);
                af[mi][2] = __float_as_uint(ap[4]);
                af[mi][3] = __float_as_uint(ap[8 * 36 + 4]);
            }
            #pragma unroll
            for (int ni = 0; ni < 4; ni++) {
                const float* bp = Bs + (wn + ni * 8 + g) * 36 + kk + t;
                bf[ni][0] = __float_as_uint(bp[0]);
                bf[ni][1] = __float_as_uint(bp[4]);
            }
            #pragma unroll
            for (int mi = 0; mi < 4; mi++)
                #pragma unroll
                for (int ni = 0; ni < 4; ni++)
                    mma16n8k8(acc[mi][ni], af[mi], bf[ni]);
        }
    }
}

// ---------------- kernel 3: projections via warp-mma ----------------
__global__ __launch_bounds__(256, 2) void proj_w(const float* __restrict__ bg) {
    __shared__ float As[128 * 36];
    __shared__ float Bs[128 * 36];
    float acc[4][4][4];
    #pragma unroll
    for (int a = 0; a < 4; a++)
        #pragma unroll
        for (int b = 0; b < 4; b++)
            #pragma unroll
            for (int c = 0; c < 4; c++) acc[a][b][c] = 0.0f;

    int m0 = blockIdx.x * 128, by = blockIdx.y;
    wm_mainloop(g_mln + (size_t)m0 * 256, g_wT + (size_t)(by * 128) * 256, As, Bs, acc);

    int tid = threadIdx.x, wid = tid >> 5, lane = tid & 31;
    int g = lane >> 2, t = lane & 3;
    int wm = (wid >> 2) * 64, wn = (wid & 3) * 32;
    int mat = by >> 1;
    float* dst = (mat == 0) ? g_q : (mat == 1) ? g_k : (mat == 2) ? g_v : g_g;
    const float qs = 0.17677669529663687f;
    #pragma unroll
    for (int mi = 0; mi < 4; mi++) {
        #pragma unroll
        for (int half = 0; half < 2; half++) {
            int m = m0 + wm + mi * 16 + g + half * 8;
            int s = m >> 8, rr = m & 255;
            #pragma unroll
            for (int ni = 0; ni < 4; ni++) {
                int n = (by & 1) * 128 + wn + ni * 8 + 2 * t;
                int h = n >> 5, c = n & 31;
                float v0 = acc[mi][ni][half * 2 + 0];
                float v1 = acc[mi][ni][half * 2 + 1];
                if (mat == 0) { v0 *= qs; v1 *= qs; }
                else if (mat == 3) {
                    v0 = 1.0f / (1.0f + __expf(-(v0 + bg[n])));
                    v1 = 1.0f / (1.0f + __expf(-(v1 + bg[n + 1])));
                }
                *(float2*)(dst + (((size_t)(s * NH_ + h) * R_ + rr) * CH_ + c)) =
                    make_float2(v0, v1);
            }
        }
    }
}

// ---------------- kernel 4: fused attention, register-tiled ----------------
// block per (s,h). thread(ty 0..31, tx 0..7): 8 q rows, 4-key / 4-c slices.
__global__ __launch_bounds__(256, 2) void attn2(const float* __restrict__ mask) {
    extern __shared__ float sm[];
    float* Qt = sm;                // [32][256]  Qt[c][q]
    float* Kt = sm + 8192;         // [32][36]   Kt[c][k]
    float* Vs = sm + 9344;         // [32][36]   Vs[k][c]
    float* Ps = sm + 10496;        // [32][260]  Ps[k][q]
    float* mb = sm + 18816;        // [256]

    int sh = blockIdx.x, s = sh >> 3, h = sh & 7;
    int tid = threadIdx.x;
    int ty = tid >> 3, tx = tid & 7;
    int q0 = ty * 8, c0 = tx * 4;

    const float* qg = g_q + (size_t)sh * R_ * CH_;
    const float* kg = g_k + (size_t)sh * R_ * CH_;
    const float* vg = g_v + (size_t)sh * R_ * CH_;

    {   // transpose Q[q][c] -> Qt[c][q]
        const float4* qp = (const float4*)(qg + (size_t)tid * CH_);
        #pragma unroll
        for (int j = 0; j < 8; j++) {
            float4 v = qp[j];
            Qt[(j * 4 + 0) * 256 + tid] = v.x;
            Qt[(j * 4 + 1) * 256 + tid] = v.y;
            Qt[(j * 4 + 2) * 256 + tid] = v.z;
            Qt[(j * 4 + 3) * 256 + tid] = v.w;
        }
    }
    mb[tid] = 1e9f * (mask[s * R_ + tid] - 1.0f);

    float m_[8], l_[8], O[8][4];
    #pragma unroll
    for (int i = 0; i < 8; i++) {
        m_[i] = -1e30f; l_[i] = 0.0f;
        O[i][0] = O[i][1] = O[i][2] = O[i][3] = 0.0f;
    }
    const float* zrow = g_zb + (size_t)h * R_ * R_;

    #pragma unroll 1
    for (int k0 = 0; k0 < R_; k0 += 32) {
        __syncthreads();
        {   // stage K (transpose to Kt[c][k]) and V (direct Vs[k][c])
            int k = tid >> 3, c4 = (tid & 7) * 4;
            float4 kv = *(const float4*)(kg + (size_t)(k0 + k) * CH_ + c4);
            Kt[(c4 + 0) * 36 + k] = kv.x;
            Kt[(c4 + 1) * 36 + k] = kv.y;
            Kt[(c4 + 2) * 36 + k] = kv.z;
            Kt[(c4 + 3) * 36 + k] = kv.w;
            float4 vv = *(const float4*)(vg + (size_t)(k0 + k) * CH_ + c4);
            *(float4*)(Vs + k * 36 + c4) = vv;
        }
        __syncthreads();

        float p[8][4];
        #pragma unroll
        for (int i = 0; i < 8; i++) { p[i][0] = p[i][1] = p[i][2] = p[i][3] = 0.0f; }
        #pragma unroll 8
        for (int c = 0; c < 32; c++) {
            float4 kb  = *(const float4*)(Kt + c * 36 + tx * 4);
            float4 qa0 = *(const float4*)(Qt + c * 256 + q0);
            float4 qa1 = *(const float4*)(Qt + c * 256 + q0 + 4);
            float ra[8] = {qa0.x, qa0.y, qa0.z, qa0.w, qa1.x, qa1.y, qa1.z, qa1.w};
            #pragma unroll
            for (int i = 0; i < 8; i++) {
                p[i][0] = fmaf(ra[i], kb.x, p[i][0]);
                p[i][1] = fmaf(ra[i], kb.y, p[i][1]);
                p[i][2] = fmaf(ra[i], kb.z, p[i][2]);
                p[i][3] = fmaf(ra[i], kb.w, p[i][3]);
            }
        }
        float4 mbv = *(const float4*)(mb + k0 + tx * 4);
        #pragma unroll
        for (int i = 0; i < 8; i++) {
            float4 zb4 = *(const float4*)(zrow + (size_t)(q0 + i) * R_ + k0 + tx * 4);
            p[i][0] += mbv.x + zb4.x;
            p[i][1] += mbv.y + zb4.y;
            p[i][2] += mbv.z + zb4.z;
            p[i][3] += mbv.w + zb4.w;
            float tm = fmaxf(fmaxf(p[i][0], p[i][1]), fmaxf(p[i][2], p[i][3]));
            tm = fmaxf(tm, __shfl_xor_sync(0xffffffffu, tm, 1));
            tm = fmaxf(tm, __shfl_xor_sync(0xffffffffu, tm, 2));
            tm = fmaxf(tm, __shfl_xor_sync(0xffffffffu, tm, 4));
            float nm = fmaxf(m_[i], tm);
            float corr = __expf(m_[i] - nm);
            m_[i] = nm;
            l_[i] *= corr;
            O[i][0] *= corr; O[i][1] *= corr; O[i][2] *= corr; O[i][3] *= corr;
            #pragma unroll
            for (int j = 0; j < 4; j++) {
                float pe = __expf(p[i][j] - nm);
                l_[i] += pe;
                Ps[(tx * 4 + j) * 260 + q0 + i] = pe;
            }
        }
        __syncthreads();
        #pragma unroll 8
        for (int kk = 0; kk < 32; kk++) {
            float4 a0 = *(const float4*)(Ps + kk * 260 + q0);
            float4 a1 = *(const float4*)(Ps + kk * 260 + q0 + 4);
            float4 vb = *(const float4*)(Vs + kk * 36 + c0);
            float ra[8] = {a0.x, a0.y, a0.z, a0.w, a1.x, a1.y, a1.z, a1.w};
            #pragma unroll
            for (int i = 0; i < 8; i++) {
                O[i][0] = fmaf(ra[i], vb.x, O[i][0]);
                O[i][1] = fmaf(ra[i], vb.y, O[i][1]);
                O[i][2] = fmaf(ra[i], vb.z, O[i][2]);
                O[i][3] = fmaf(ra[i], vb.w, O[i][3]);
            }
        }
    }

    const float* gg = g_g + (size_t)sh * R_ * CH_;
    #pragma unroll
    for (int i = 0; i < 8; i++) {
        float lf = l_[i];
        lf += __shfl_xor_sync(0xffffffffu, lf, 1);
        lf += __shfl_xor_sync(0xffffffffu, lf, 2);
        lf += __shfl_xor_sync(0xffffffffu, lf, 4);
        float inv = 1.0f / lf;
        int q = q0 + i;
        float4 gv = *(const float4*)(gg + (size_t)q * CH_ + c0);
        float4 o;
        o.x = rtf32(O[i][0] * inv * gv.x);
        o.y = rtf32(O[i][1] * inv * gv.y);
        o.z = rtf32(O[i][2] * inv * gv.z);
        o.w = rtf32(O[i][3] * inv * gv.w);
        *(float4*)(g_og + (size_t)(s * R_ + q) * HC_ + h * CH_ + c0) = o;
    }
}

// ---------------- kernel 5: output GEMM via warp-mma ----------------
__global__ __launch_bounds__(256, 2) void out_w(const float* __restrict__ bo,
                                                float* __restrict__ out) {
    __shared__ float As[128 * 36];
    __shared__ float Bs[128 * 36];
    float acc[4][4][4];
    #pragma unroll
    for (int a = 0; a < 4; a++)
        #pragma unroll
        for (int b = 0; b < 4; b++)
            #pragma unroll
            for (int c = 0; c < 4; c++) acc[a][b][c] = 0.0f;

    int m0 = blockIdx.x * 128, n0 = blockIdx.y * 128;
    wm_mainloop(g_og + (size_t)m0 * 256, g_woT + (size_t)n0 * 256, As, Bs, acc);

    int tid = threadIdx.x, wid = tid >> 5, lane = tid & 31;
    int g = lane >> 2, t = lane & 3;
    int wm = (wid >> 2) * 64, wn = (wid & 3) * 32;
    #pragma unroll
    for (int mi = 0; mi < 4; mi++) {
        #pragma unroll
        for (int half = 0; half < 2; half++) {
            int m = m0 + wm + mi * 16 + g + half * 8;
            #pragma unroll
            for (int ni = 0; ni < 4; ni++) {
                int n = n0 + wn + ni * 8 + 2 * t;
                float v0 = acc[mi][ni][half * 2 + 0] + bo[n];
                float v1 = acc[mi][ni][half * 2 + 1] + bo[n + 1];
                *(float2*)(out + (size_t)m * CM_ + n) = make_float2(v0, v1);
            }
        }
    }
}

// ---------------- launch ----------------
extern "C" void kernel_launch(void* const* d_in, const int* in_sizes, int n_in,
                              void* d_out, int out_size) {
    (void)in_sizes; (void)n_in; (void)out_size;
    const float* m      = (const float*)d_in[0];
    const float* z      = (const float*)d_in[1];
    const float* mask   = (const float*)d_in[2];
    const float* ln_m_g = (const float*)d_in[3];
    const float* ln_m_b = (const float*)d_in[4];
    const float* ln_z_g = (const float*)d_in[5];
    const float* ln_z_b = (const float*)d_in[6];
    const float* w_z    = (const float*)d_in[7];
    const float* wq     = (const float*)d_in[8];
    const float* wk     = (const float*)d_in[9];
    const float* wv     = (const float*)d_in[10];
    const float* wg     = (const float*)d_in[11];
    const float* bg     = (const float*)d_in[12];
    const float* wo     = (const float*)d_in[13];
    const float* bo     = (const float*)d_in[14];
    float* out = (float*)d_out;

    const int attn_smem = 19072 * (int)sizeof(float);
    cudaFuncSetAttribute(attn2, cudaFuncAttributeMaxDynamicSharedMemorySize, attn_smem);

    ln_m_kernel<<<MTOT / 8, 256>>>(m, ln_m_g, ln_m_b);
    zbias_kernel<<<R_ * R_ / 8, 256>>>(z, ln_z_g, ln_z_b, w_z);
    wtrans_kernel<<<dim3(8, 8, 5), 256>>>(wq, wk, wv, wg, wo);
    proj_w<<<dim3(MTOT / 128, 8), 256>>>(bg);
    attn2<<<S_ * NH_, 256, attn_smem>>>(mask);
    out_w<<<dim3(MTOT / 128, 2), 256>>>(bo, out);
}

// round 7
// speedup vs baseline: 1.6980x; 1.0706x over previous
#include <cuda_runtime.h>
#include <math.h>
#include <stdint.h>

#define S_   128
#define R_   256
#define CM_  256
#define CZ_  128
#define NH_  8
#define CH_  32
#define HC_  256
#define MTOT (S_*R_)

typedef unsigned long long u64;

// ---------------- scratch ----------------
__device__ float g_mln[MTOT*CM_];            // LN(m), tf32-rounded   [m][k]
__device__ float g_q[NH_*S_*R_*CH_];         // [s*8+h][r][c]
__device__ float g_k[NH_*S_*R_*CH_];
__device__ float g_v[NH_*S_*R_*CH_];
__device__ float g_g[NH_*S_*R_*CH_];
__device__ float g_og[MTOT*HC_];             // (o*g), tf32-rounded   [m][hc]
__device__ float g_zb[NH_*R_*R_];            // pair bias [h][q][k]
__device__ float g_wT[4*HC_*CM_];            // [mat*256+n][k], tf32-rounded
__device__ float g_woT[CM_*HC_];             // [n][k], tf32-rounded

static __device__ __forceinline__ float rtf32(float x) {
    uint32_t u; asm("cvt.rn.tf32.f32 %0, %1;" : "=r"(u) : "f"(x));
    return __uint_as_float(u);
}
static __device__ __forceinline__ void mma16n8k8(float* d, const uint32_t* a, const uint32_t* b) {
    asm volatile("mma.sync.aligned.m16n8k8.row.col.f32.tf32.tf32.f32 "
        "{%0,%1,%2,%3}, {%4,%5,%6,%7}, {%8,%9}, {%0,%1,%2,%3};"
        : "+f"(d[0]), "+f"(d[1]), "+f"(d[2]), "+f"(d[3])
        : "r"(a[0]), "r"(a[1]), "r"(a[2]), "r"(a[3]), "r"(b[0]), "r"(b[1]));
}
// packed fp32x2 ops (Blackwell; SASS FFMA2) — exact IEEE fp32 lanewise
#define FMA2(d, a, b) asm("fma.rn.f32x2 %0, %1, %2, %0;" : "+l"(d) : "l"(a), "l"(b))
#define MUL2I(d, c)   asm("mul.rn.f32x2 %0, %0, %1;"     : "+l"(d) : "l"(c))
#define PACK2(d, lo, hi)   asm("mov.b64 %0, {%1, %2};" : "=l"(d) : "f"(lo), "f"(hi))
#define UNPACK2(lo, hi, s) asm("mov.b64 {%0, %1}, %2;" : "=f"(lo), "=f"(hi) : "l"(s))
// cp.async 16B
#define CPA16(dst_u32, src) \
    asm volatile("cp.async.ca.shared.global [%0], [%1], 16;" :: "r"(dst_u32), "l"(src))
#define CPA_COMMIT() asm volatile("cp.async.commit_group;" ::: "memory")
#define CPA_WAIT1()  asm volatile("cp.async.wait_group 1;" ::: "memory")
#define CPA_WAIT0()  asm volatile("cp.async.wait_group 0;" ::: "memory")
static __device__ __forceinline__ uint32_t sptr(const void* p) {
    return (uint32_t)__cvta_generic_to_shared(p);
}

// ---------------- kernel 1: LayerNorm(m) -> tf32-rounded ----------------
__global__ __launch_bounds__(256) void ln_m_kernel(const float* __restrict__ m,
                                                   const float* __restrict__ g,
                                                   const float* __restrict__ b) {
    int warp = threadIdx.x >> 5, lane = threadIdx.x & 31;
    int row = blockIdx.x * 8 + warp;
    const float* x = m + (size_t)row * CM_;
    float4 a = *(const float4*)(x + lane * 4);
    float4 c = *(const float4*)(x + 128 + lane * 4);
    float s  = a.x + a.y + a.z + a.w + c.x + c.y + c.z + c.w;
    float ss = a.x*a.x + a.y*a.y + a.z*a.z + a.w*a.w
             + c.x*c.x + c.y*c.y + c.z*c.z + c.w*c.w;
    #pragma unroll
    for (int o = 16; o > 0; o >>= 1) {
        s  += __shfl_xor_sync(0xffffffffu, s,  o);
        ss += __shfl_xor_sync(0xffffffffu, ss, o);
    }
    float mu   = s * (1.0f / CM_);
    float var  = ss * (1.0f / CM_) - mu * mu;
    float rstd = rsqrtf(var + 1e-5f);
    float* y = g_mln + (size_t)row * CM_;
    {
        float4 gg = *(const float4*)(g + lane * 4);
        float4 bb = *(const float4*)(b + lane * 4);
        float4 r;
        r.x = rtf32((a.x - mu) * rstd * gg.x + bb.x);
        r.y = rtf32((a.y - mu) * rstd * gg.y + bb.y);
        r.z = rtf32((a.z - mu) * rstd * gg.z + bb.z);
        r.w = rtf32((a.w - mu) * rstd * gg.w + bb.w);
        *(float4*)(y + lane * 4) = r;
    }
    {
        float4 gg = *(const float4*)(g + 128 + lane * 4);
        float4 bb = *(const float4*)(b + 128 + lane * 4);
        float4 r;
        r.x = rtf32((c.x - mu) * rstd * gg.x + bb.x);
        r.y = rtf32((c.y - mu) * rstd * gg.y + bb.y);
        r.z = rtf32((c.z - mu) * rstd * gg.z + bb.z);
        r.w = rtf32((c.w - mu) * rstd * gg.w + bb.w);
        *(float4*)(y + 128 + lane * 4) = r;
    }
}

// ---------------- kernel 2: pair bias ----------------
__global__ __launch_bounds__(256) void zbias_kernel(const float* __restrict__ z,
                                                    const float* __restrict__ gz,
                                                    const float* __restrict__ bz,
                                                    const float* __restrict__ wz) {
    __shared__ float wsT[NH_ * CZ_];
    int tid = threadIdx.x;
    for (int i = tid; i < NH_ * CZ_; i += 256) {
        int h = i / CZ_, e = i % CZ_;
        wsT[i] = wz[e * NH_ + h];
    }
    __syncthreads();
    int warp = tid >> 5, lane = tid & 31;
    int p = blockIdx.x * 8 + warp;
    const float* x = z + (size_t)p * CZ_;
    float4 a = *(const float4*)(x + lane * 4);
    float s  = a.x + a.y + a.z + a.w;
    float ss = a.x*a.x + a.y*a.y + a.z*a.z + a.w*a.w;
    #pragma unroll
    for (int o = 16; o > 0; o >>= 1) {
        s  += __shfl_xor_sync(0xffffffffu, s,  o);
        ss += __shfl_xor_sync(0xffffffffu, ss, o);
    }
    float mu   = s * (1.0f / CZ_);
    float var  = ss * (1.0f / CZ_) - mu * mu;
    float rstd = rsqrtf(var + 1e-5f);
    int col = lane * 4;
    float4 gg = *(const float4*)(gz + col);
    float4 bb = *(const float4*)(bz + col);
    float n0 = (a.x - mu) * rstd * gg.x + bb.x;
    float n1 = (a.y - mu) * rstd * gg.y + bb.y;
    float n2 = (a.z - mu) * rstd * gg.z + bb.z;
    float n3 = (a.w - mu) * rstd * gg.w + bb.w;
    float keep = 0.0f;
    #pragma unroll
    for (int h = 0; h < NH_; h++) {
        float4 w = *(const float4*)(&wsT[h * CZ_ + col]);
        float part = n0 * w.x + n1 * w.y + n2 * w.z + n3 * w.w;
        #pragma unroll
        for (int o = 16; o > 0; o >>= 1)
            part += __shfl_xor_sync(0xffffffffu, part, o);
        if (lane == h) keep = part;
    }
    if (lane < NH_) g_zb[(size_t)lane * R_ * R_ + p] = keep;
}

// ---------------- kernel 2b: weight transpose + tf32 round ----------------
__global__ __launch_bounds__(256) void wtrans_kernel(const float* __restrict__ wq,
                                                     const float* __restrict__ wk,
                                                     const float* __restrict__ wv,
                                                     const float* __restrict__ wg,
                                                     const float* __restrict__ wo) {
    __shared__ float t[32][33];
    int mat = blockIdx.z;
    const float* W = (mat == 0) ? wq : (mat == 1) ? wk : (mat == 2) ? wv : (mat == 3) ? wg : wo;
    float* D = (mat < 4) ? (g_wT + (size_t)mat * HC_ * CM_) : g_woT;
    int bx = blockIdx.x, by = blockIdx.y;
    int tx = threadIdx.x & 31, ty8 = threadIdx.x >> 5;
    #pragma unroll
    for (int r = 0; r < 32; r += 8)
        t[ty8 + r][tx] = W[(size_t)(by * 32 + ty8 + r) * 256 + bx * 32 + tx];
    __syncthreads();
    #pragma unroll
    for (int r = 0; r < 32; r += 8)
        D[(size_t)(bx * 32 + ty8 + r) * 256 + by * 32 + tx] = rtf32(t[tx][ty8 + r]);
}

// ---------------- warp-mma tf32 mainloop, cp.async double-buffered ----------------
// dynamic smem: 2 stages x (A[128*36] + B[128*36]) = 18432 floats
static __device__ __forceinline__ void stage_cp(float* dA, const float* sA,
                                                float* dB, const float* sB) {
    #pragma unroll
    for (int j = 0; j < 16; j += 4) {
        CPA16(sptr(dA + j), sA + j);
        CPA16(sptr(dB + j), sB + j);
    }
}
static __device__ __forceinline__ void wm_mainloop(const float* __restrict__ Arow0,
                                                   const float* __restrict__ Brow0,
                                                   float* sm, float acc[4][4][4]) {
    int tid = threadIdx.x;
    int wid = tid >> 5, lane = tid & 31;
    int g = lane >> 2, t = lane & 3;
    int wm = (wid >> 2) * 64, wn = (wid & 3) * 32;
    int lrow = tid >> 1, lk = (tid & 1) * 16;
    const float* Ag = Arow0 + (size_t)lrow * 256 + lk;
    const float* Bg = Brow0 + (size_t)lrow * 256 + lk;
    float* dA0 = sm + lrow * 36 + lk;
    float* dB0 = sm + 4608 + lrow * 36 + lk;

    stage_cp(dA0, Ag, dB0, Bg);
    CPA_COMMIT();
    #pragma unroll 1
    for (int kc = 0; kc < 8; kc++) {
        if (kc < 7) {
            int st = (kc + 1) & 1;
            stage_cp(dA0 + st * 9216, Ag + (kc + 1) * 32, dB0 + st * 9216, Bg + (kc + 1) * 32);
            CPA_COMMIT();
            CPA_WAIT1();
        } else {
            CPA_WAIT0();
        }
        __syncthreads();
        const float* As = sm + (kc & 1) * 9216;
        const float* Bs = As + 4608;
        #pragma unroll
        for (int kk = 0; kk < 32; kk += 8) {
            uint32_t af[4][4], bf[4][2];
            #pragma unroll
            for (int mi = 0; mi < 4; mi++) {
                const float* ap = As + (wm + mi * 16 + g) * 36 + kk + t;
                af[mi][0] = __float_as_uint(ap[0]);
                af[mi][1] = __float_as_uint(ap[8 * 36]);
                af[mi][2] = __float_as_uint(ap[4]);
                af[mi][3] = __float_as_uint(ap[8 * 36 + 4]);
            }
            #pragma unroll
            for (int ni = 0; ni < 4; ni++) {
                const float* bp = Bs + (wn + ni * 8 + g) * 36 + kk + t;
                bf[ni][0] = __float_as_uint(bp[0]);
                bf[ni][1] = __float_as_uint(bp[4]);
            }
            #pragma unroll
            for (int mi = 0; mi < 4; mi++)
                #pragma unroll
                for (int ni = 0; ni < 4; ni++)
                    mma16n8k8(acc[mi][ni], af[mi], bf[ni]);
        }
        __syncthreads();
    }
}

// ---------------- kernel 3: projections via warp-mma ----------------
__global__ __launch_bounds__(256, 2) void proj_w(const float* __restrict__ bg) {
    extern __shared__ float smd[];
    float acc[4][4][4];
    #pragma unroll
    for (int a = 0; a < 4; a++)
        #pragma unroll
        for (int b = 0; b < 4; b++)
            #pragma unroll
            for (int c = 0; c < 4; c++) acc[a][b][c] = 0.0f;

    int m0 = blockIdx.x * 128, by = blockIdx.y;
    wm_mainloop(g_mln + (size_t)m0 * 256, g_wT + (size_t)(by * 128) * 256, smd, acc);

    int tid = threadIdx.x, wid = tid >> 5, lane = tid & 31;
    int g = lane >> 2, t = lane & 3;
    int wm = (wid >> 2) * 64, wn = (wid & 3) * 32;
    int mat = by >> 1;
    float* dst = (mat == 0) ? g_q : (mat == 1) ? g_k : (mat == 2) ? g_v : g_g;
    const float qs = 0.17677669529663687f;
    #pragma unroll
    for (int mi = 0; mi < 4; mi++) {
        #pragma unroll
        for (int half = 0; half < 2; half++) {
            int m = m0 + wm + mi * 16 + g + half * 8;
            int s = m >> 8, rr = m & 255;
            #pragma unroll
            for (int ni = 0; ni < 4; ni++) {
                int n = (by & 1) * 128 + wn + ni * 8 + 2 * t;
                int h = n >> 5, c = n & 31;
                float v0 = acc[mi][ni][half * 2 + 0];
                float v1 = acc[mi][ni][half * 2 + 1];
                if (mat == 0) { v0 *= qs; v1 *= qs; }
                else if (mat == 3) {
                    v0 = 1.0f / (1.0f + __expf(-(v0 + bg[n])));
                    v1 = 1.0f / (1.0f + __expf(-(v1 + bg[n + 1])));
                }
                *(float2*)(dst + (((size_t)(s * NH_ + h) * R_ + rr) * CH_ + c)) =
                    make_float2(v0, v1);
            }
        }
    }
}

// ---------------- kernel 4: fused attention, f32x2 register-tiled ----------------
// block per (s,h). thread(ty 0..31, tx 0..7): 8 q rows (4 packed pairs), 4-key / 4-c slices.
__global__ __launch_bounds__(256, 2) void attn2(const float* __restrict__ mask) {
    extern __shared__ float sm[];
    float* Qt = sm;                // [32][256]  Qt[c][q]
    float* Kt = sm + 8192;         // [32][36]   Kt[c][k]
    float* Vs = sm + 9344;         // [32][36]   Vs[k][c]
    float* Ps = sm + 10496;        // [32][260]  Ps[k][q]
    float* mb = sm + 18816;        // [256]

    int sh = blockIdx.x, s = sh >> 3, h = sh & 7;
    int tid = threadIdx.x;
    int ty = tid >> 3, tx = tid & 7;
    int q0 = ty * 8, c0 = tx * 4;

    const float* qg = g_q + (size_t)sh * R_ * CH_;
    const float* kg = g_k + (size_t)sh * R_ * CH_;
    const float* vg = g_v + (size_t)sh * R_ * CH_;

    {   // transpose Q[q][c] -> Qt[c][q]
        const float4* qp = (const float4*)(qg + (size_t)tid * CH_);
        #pragma unroll
        for (int j = 0; j < 8; j++) {
            float4 v = qp[j];
            Qt[(j * 4 + 0) * 256 + tid] = v.x;
            Qt[(j * 4 + 1) * 256 + tid] = v.y;
            Qt[(j * 4 + 2) * 256 + tid] = v.z;
            Qt[(j * 4 + 3) * 256 + tid] = v.w;
        }
    }
    mb[tid] = 1e9f * (mask[s * R_ + tid] - 1.0f);

    float m_[8], l_[8];
    u64 O2[4][4];                 // O2[ip][j] = (O[2ip][j], O[2ip+1][j])
    #pragma unroll
    for (int i = 0; i < 8; i++) { m_[i] = -1e30f; l_[i] = 0.0f; }
    #pragma unroll
    for (int ip = 0; ip < 4; ip++)
        #pragma unroll
        for (int j = 0; j < 4; j++) O2[ip][j] = 0ull;

    const float* zrow = g_zb + (size_t)h * R_ * R_;

    #pragma unroll 1
    for (int k0 = 0; k0 < R_; k0 += 32) {
        __syncthreads();
        {   // stage K (transpose to Kt[c][k]) and V (direct Vs[k][c])
            int k = tid >> 3, c4 = (tid & 7) * 4;
            float4 kv = *(const float4*)(kg + (size_t)(k0 + k) * CH_ + c4);
            Kt[(c4 + 0) * 36 + k] = kv.x;
            Kt[(c4 + 1) * 36 + k] = kv.y;
            Kt[(c4 + 2) * 36 + k] = kv.z;
            Kt[(c4 + 3) * 36 + k] = kv.w;
            float4 vv = *(const float4*)(vg + (size_t)(k0 + k) * CH_ + c4);
            *(float4*)(Vs + k * 36 + c4) = vv;
        }
        __syncthreads();

        // QK^T: pq[ip][j] = packed logits for q-pair ip, key slot j
        u64 pq[4][4];
        #pragma unroll
        for (int ip = 0; ip < 4; ip++)
            #pragma unroll
            for (int j = 0; j < 4; j++) pq[ip][j] = 0ull;
        #pragma unroll 8
        for (int c = 0; c < 32; c++) {
            float4 kb = *(const float4*)(Kt + c * 36 + tx * 4);
            u64 kd[4];
            PACK2(kd[0], kb.x, kb.x); PACK2(kd[1], kb.y, kb.y);
            PACK2(kd[2], kb.z, kb.z); PACK2(kd[3], kb.w, kb.w);
            ulonglong2 qa = *(const ulonglong2*)(Qt + c * 256 + q0);
            ulonglong2 qb = *(const ulonglong2*)(Qt + c * 256 + q0 + 4);
            u64 qp_[4] = {qa.x, qa.y, qb.x, qb.y};
            #pragma unroll
            for (int ip = 0; ip < 4; ip++) {
                FMA2(pq[ip][0], qp_[ip], kd[0]);
                FMA2(pq[ip][1], qp_[ip], kd[1]);
                FMA2(pq[ip][2], qp_[ip], kd[2]);
                FMA2(pq[ip][3], qp_[ip], kd[3]);
            }
        }

        float4 mbv = *(const float4*)(mb + k0 + tx * 4);
        #pragma unroll
        for (int ip = 0; ip < 4; ip++) {
            int ia = 2 * ip, ib = 2 * ip + 1;
            float pa[4], pb[4];
            #pragma unroll
            for (int j = 0; j < 4; j++) UNPACK2(pa[j], pb[j], pq[ip][j]);
            float4 za = *(const float4*)(zrow + (size_t)(q0 + ia) * R_ + k0 + tx * 4);
            float4 zb = *(const float4*)(zrow + (size_t)(q0 + ib) * R_ + k0 + tx * 4);
            pa[0] += mbv.x + za.x; pa[1] += mbv.y + za.y;
            pa[2] += mbv.z + za.z; pa[3] += mbv.w + za.w;
            pb[0] += mbv.x + zb.x; pb[1] += mbv.y + zb.y;
            pb[2] += mbv.z + zb.z; pb[3] += mbv.w + zb.w;
            // row ia
            float ta = fmaxf(fmaxf(pa[0], pa[1]), fmaxf(pa[2], pa[3]));
            ta = fmaxf(ta, __shfl_xor_sync(0xffffffffu, ta, 1));
            ta = fmaxf(ta, __shfl_xor_sync(0xffffffffu, ta, 2));
            ta = fmaxf(ta, __shfl_xor_sync(0xffffffffu, ta, 4));
            float nma = fmaxf(m_[ia], ta);
            float ca = __expf(m_[ia] - nma);
            m_[ia] = nma; l_[ia] *= ca;
            // row ib
            float tb = fmaxf(fmaxf(pb[0], pb[1]), fmaxf(pb[2], pb[3]));
            tb = fmaxf(tb, __shfl_xor_sync(0xffffffffu, tb, 1));
            tb = fmaxf(tb, __shfl_xor_sync(0xffffffffu, tb, 2));
            tb = fmaxf(tb, __shfl_xor_sync(0xffffffffu, tb, 4));
            float nmb = fmaxf(m_[ib], tb);
            float cb = __expf(m_[ib] - nmb);
            m_[ib] = nmb; l_[ib] *= cb;
            // rescale packed output accumulators
            u64 c2; PACK2(c2, ca, cb);
            MUL2I(O2[ip][0], c2); MUL2I(O2[ip][1], c2);
            MUL2I(O2[ip][2], c2); MUL2I(O2[ip][3], c2);
            // exp + paired Ps stores
            #pragma unroll
            for (int j = 0; j < 4; j++) {
                float ea = __expf(pa[j] - nma);
                float eb = __expf(pb[j] - nmb);
                l_[ia] += ea; l_[ib] += eb;
                *(float2*)(Ps + (tx * 4 + j) * 260 + q0 + 2 * ip) = make_float2(ea, eb);
            }
        }
        __syncthreads();

        // AV: O2[ip][j] += P(q-pair) * V[k][c0+j]
        #pragma unroll 8
        for (int kk = 0; kk < 32; kk++) {
            ulonglong2 a0 = *(const ulonglong2*)(Ps + kk * 260 + q0);
            ulonglong2 a1 = *(const ulonglong2*)(Ps + kk * 260 + q0 + 4);
            u64 aq[4] = {a0.x, a0.y, a1.x, a1.y};
            float4 vb = *(const float4*)(Vs + kk * 36 + c0);
            u64 vd[4];
            PACK2(vd[0], vb.x, vb.x); PACK2(vd[1], vb.y, vb.y);
            PACK2(vd[2], vb.z, vb.z); PACK2(vd[3], vb.w, vb.w);
            #pragma unroll
            for (int ip = 0; ip < 4; ip++) {
                FMA2(O2[ip][0], aq[ip], vd[0]);
                FMA2(O2[ip][1], aq[ip], vd[1]);
                FMA2(O2[ip][2], aq[ip], vd[2]);
                FMA2(O2[ip][3], aq[ip], vd[3]);
            }
        }
    }

    float inv[8];
    #pragma unroll
    for (int i = 0; i < 8; i++) {
        float lf = l_[i];
        lf += __shfl_xor_sync(0xffffffffu, lf, 1);
        lf += __shfl_xor_sync(0xffffffffu, lf, 2);
        lf += __shfl_xor_sync(0xffffffffu, lf, 4);
        inv[i] = 1.0f / lf;
    }
    const float* gg = g_g + (size_t)sh * R_ * CH_;
    #pragma unroll
    for (int ip = 0; ip < 4; ip++) {
        float Oa[4], Ob[4];
        #pragma unroll
        for (int j = 0; j < 4; j++) UNPACK2(Oa[j], Ob[j], O2[ip][j]);
        #pragma unroll
        for (int half = 0; half < 2; half++) {
            int i = 2 * ip + half;
            const float* Ov = half ? Ob : Oa;
            int q = q0 + i;
            float4 gv = *(const float4*)(gg + (size_t)q * CH_ + c0);
            float4 o;
            o.x = rtf32(Ov[0] * inv[i] * gv.x);
            o.y = rtf32(Ov[1] * inv[i] * gv.y);
            o.z = rtf32(Ov[2] * inv[i] * gv.z);
            o.w = rtf32(Ov[3] * inv[i] * gv.w);
            *(float4*)(g_og + (size_t)(s * R_ + q) * HC_ + h * CH_ + c0) = o;
        }
    }
}

// ---------------- kernel 5: output GEMM via warp-mma ----------------
__global__ __launch_bounds__(256, 2) void out_w(const float* __restrict__ bo,
                                                float* __restrict__ out) {
    extern __shared__ float smd[];
    float acc[4][4][4];
    #pragma unroll
    for (int a = 0; a < 4; a++)
        #pragma unroll
        for (int b = 0; b < 4; b++)
            #pragma unroll
            for (int c = 0; c < 4; c++) acc[a][b][c] = 0.0f;

    int m0 = blockIdx.x * 128, n0 = blockIdx.y * 128;
    wm_mainloop(g_og + (size_t)m0 * 256, g_woT + (size_t)n0 * 256, smd, acc);

    int tid = threadIdx.x, wid = tid >> 5, lane = tid & 31;
    int g = lane >> 2, t = lane & 3;
    int wm = (wid >> 2) * 64, wn = (wid & 3) * 32;
    #pragma unroll
    for (int mi = 0; mi < 4; mi++) {
        #pragma unroll
        for (int half = 0; half < 2; half++) {
            int m = m0 + wm + mi * 16 + g + half * 8;
            #pragma unroll
            for (int ni = 0; ni < 4; ni++) {
                int n = n0 + wn + ni * 8 + 2 * t;
                float v0 = acc[mi][ni][half * 2 + 0] + bo[n];
                float v1 = acc[mi][ni][half * 2 + 1] + bo[n + 1];
                *(float2*)(out + (size_t)m * CM_ + n) = make_float2(v0, v1);
            }
        }
    }
}

// ---------------- launch ----------------
extern "C" void kernel_launch(void* const* d_in, const int* in_sizes, int n_in,
                              void* d_out, int out_size) {
    (void)in_sizes; (void)n_in; (void)out_size;
    const float* m      = (const float*)d_in[0];
    const float* z      = (const float*)d_in[1];
    const float* mask   = (const float*)d_in[2];
    const float* ln_m_g = (const float*)d_in[3];
    const float* ln_m_b = (const float*)d_in[4];
    const float* ln_z_g = (const float*)d_in[5];
    const float* ln_z_b = (const float*)d_in[6];
    const float* w_z    = (const float*)d_in[7];
    const float* wq     = (const float*)d_in[8];
    const float* wk     = (const float*)d_in[9];
    const float* wv     = (const float*)d_in[10];
    const float* wg     = (const float*)d_in[11];
    const float* bg     = (const float*)d_in[12];
    const float* wo     = (const float*)d_in[13];
    const float* bo     = (const float*)d_in[14];
    float* out = (float*)d_out;

    const int gemm_smem = 73728;  // 2 stages x (A+B) x 128x36 floats
    cudaFuncSetAttribute(proj_w, cudaFuncAttributeMaxDynamicSharedMemorySize, gemm_smem);
    cudaFuncSetAttribute(out_w,  cudaFuncAttributeMaxDynamicSharedMemorySize, gemm_smem);
    const int attn_smem = 19072 * (int)sizeof(float);
    cudaFuncSetAttribute(attn2, cudaFuncAttributeMaxDynamicSharedMemorySize, attn_smem);

    ln_m_kernel<<<MTOT / 8, 256>>>(m, ln_m_g, ln_m_b);
    zbias_kernel<<<R_ * R_ / 8, 256>>>(z, ln_z_g, ln_z_b, w_z);
    wtrans_kernel<<<dim3(8, 8, 5), 256>>>(wq, wk, wv, wg, wo);
    proj_w<<<dim3(MTOT / 128, 8), 256, gemm_smem>>>(bg);
    attn2<<<S_ * NH_, 256, attn_smem>>>(mask);
    out_w<<<dim3(MTOT / 128, 2), 256, gemm_smem>>>(bo, out);
}

// round 8
// speedup vs baseline: 1.7883x; 1.0532x over previous
#include <cuda_runtime.h>
#include <math.h>
#include <stdint.h>

#define S_   128
#define R_   256
#define CM_  256
#define CZ_  128
#define NH_  8
#define CH_  32
#define HC_  256
#define MTOT (S_*R_)

typedef unsigned long long u64;

// ---------------- scratch ----------------
__device__ float g_mln[MTOT*CM_];            // LN(m), tf32-rounded   [m][k]
__device__ float g_q[NH_*S_*R_*CH_];         // [s*8+h][r][c]
__device__ float g_k[NH_*S_*R_*CH_];
__device__ float g_v[NH_*S_*R_*CH_];
__device__ float g_g[NH_*S_*R_*CH_];
__device__ float g_og[MTOT*HC_];             // (o*g), tf32-rounded   [m][hc]
__device__ float g_zb[NH_*R_*R_];            // pair bias [h][q][k]
__device__ float g_wT[4*HC_*CM_];            // [mat*256+n][k], tf32-rounded
__device__ float g_woT[CM_*HC_];             // [n][k], tf32-rounded

static __device__ __forceinline__ float rtf32(float x) {
    uint32_t u; asm("cvt.rn.tf32.f32 %0, %1;" : "=r"(u) : "f"(x));
    return __uint_as_float(u);
}
static __device__ __forceinline__ void mma16n8k8(float* d, const uint32_t* a, const uint32_t* b) {
    asm volatile("mma.sync.aligned.m16n8k8.row.col.f32.tf32.tf32.f32 "
        "{%0,%1,%2,%3}, {%4,%5,%6,%7}, {%8,%9}, {%0,%1,%2,%3};"
        : "+f"(d[0]), "+f"(d[1]), "+f"(d[2]), "+f"(d[3])
        : "r"(a[0]), "r"(a[1]), "r"(a[2]), "r"(a[3]), "r"(b[0]), "r"(b[1]));
}
#define LDSM4(r0, r1, r2, r3, a) \
    asm volatile("ldmatrix.sync.aligned.m8n8.x4.shared.b16 {%0,%1,%2,%3}, [%4];" \
        : "=r"(r0), "=r"(r1), "=r"(r2), "=r"(r3) : "r"(a))
// packed fp32x2 ops (Blackwell; SASS FFMA2) — exact IEEE fp32 lanewise
#define FMA2(d, a, b) asm("fma.rn.f32x2 %0, %1, %2, %0;" : "+l"(d) : "l"(a), "l"(b))
#define MUL2I(d, c)   asm("mul.rn.f32x2 %0, %0, %1;"     : "+l"(d) : "l"(c))
#define PACK2(d, lo, hi)   asm("mov.b64 %0, {%1, %2};" : "=l"(d) : "f"(lo), "f"(hi))
#define UNPACK2(lo, hi, s) asm("mov.b64 {%0, %1}, %2;" : "=f"(lo), "=f"(hi) : "l"(s))
// cp.async 16B
#define CPA16(dst_u32, src) \
    asm volatile("cp.async.ca.shared.global [%0], [%1], 16;" :: "r"(dst_u32), "l"(src))
#define CPA_COMMIT() asm volatile("cp.async.commit_group;" ::: "memory")
#define CPA_WAIT1()  asm volatile("cp.async.wait_group 1;" ::: "memory")
#define CPA_WAIT0()  asm volatile("cp.async.wait_group 0;" ::: "memory")
static __device__ __forceinline__ uint32_t sptr(const void* p) {
    return (uint32_t)__cvta_generic_to_shared(p);
}

// ---------------- kernel 1: LayerNorm(m) -> tf32-rounded ----------------
__global__ __launch_bounds__(256) void ln_m_kernel(const float* __restrict__ m,
                                                   const float* __restrict__ g,
                                                   const float* __restrict__ b) {
    int warp = threadIdx.x >> 5, lane = threadIdx.x & 31;
    int row = blockIdx.x * 8 + warp;
    const float* x = m + (size_t)row * CM_;
    float4 a = *(const float4*)(x + lane * 4);
    float4 c = *(const float4*)(x + 128 + lane * 4);
    float s  = a.x + a.y + a.z + a.w + c.x + c.y + c.z + c.w;
    float ss = a.x*a.x + a.y*a.y + a.z*a.z + a.w*a.w
             + c.x*c.x + c.y*c.y + c.z*c.z + c.w*c.w;
    #pragma unroll
    for (int o = 16; o > 0; o >>= 1) {
        s  += __shfl_xor_sync(0xffffffffu, s,  o);
        ss += __shfl_xor_sync(0xffffffffu, ss, o);
    }
    float mu   = s * (1.0f / CM_);
    float var  = ss * (1.0f / CM_) - mu * mu;
    float rstd = rsqrtf(var + 1e-5f);
    float* y = g_mln + (size_t)row * CM_;
    {
        float4 gg = *(const float4*)(g + lane * 4);
        float4 bb = *(const float4*)(b + lane * 4);
        float4 r;
        r.x = rtf32((a.x - mu) * rstd * gg.x + bb.x);
        r.y = rtf32((a.y - mu) * rstd * gg.y + bb.y);
        r.z = rtf32((a.z - mu) * rstd * gg.z + bb.z);
        r.w = rtf32((a.w - mu) * rstd * gg.w + bb.w);
        *(float4*)(y + lane * 4) = r;
    }
    {
        float4 gg = *(const float4*)(g + 128 + lane * 4);
        float4 bb = *(const float4*)(b + 128 + lane * 4);
        float4 r;
        r.x = rtf32((c.x - mu) * rstd * gg.x + bb.x);
        r.y = rtf32((c.y - mu) * rstd * gg.y + bb.y);
        r.z = rtf32((c.z - mu) * rstd * gg.z + bb.z);
        r.w = rtf32((c.w - mu) * rstd * gg.w + bb.w);
        *(float4*)(y + 128 + lane * 4) = r;
    }
}

// ---------------- kernel 2: pair bias ----------------
__global__ __launch_bounds__(256) void zbias_kernel(const float* __restrict__ z,
                                                    const float* __restrict__ gz,
                                                    const float* __restrict__ bz,
                                                    const float* __restrict__ wz) {
    __shared__ float wsT[NH_ * CZ_];
    int tid = threadIdx.x;
    for (int i = tid; i < NH_ * CZ_; i += 256) {
        int h = i / CZ_, e = i % CZ_;
        wsT[i] = wz[e * NH_ + h];
    }
    __syncthreads();
    int warp = tid >> 5, lane = tid & 31;
    int p = blockIdx.x * 8 + warp;
    const float* x = z + (size_t)p * CZ_;
    float4 a = *(const float4*)(x + lane * 4);
    float s  = a.x + a.y + a.z + a.w;
    float ss = a.x*a.x + a.y*a.y + a.z*a.z + a.w*a.w;
    #pragma unroll
    for (int o = 16; o > 0; o >>= 1) {
        s  += __shfl_xor_sync(0xffffffffu, s,  o);
        ss += __shfl_xor_sync(0xffffffffu, ss, o);
    }
    float mu   = s * (1.0f / CZ_);
    float var  = ss * (1.0f / CZ_) - mu * mu;
    float rstd = rsqrtf(var + 1e-5f);
    int col = lane * 4;
    float4 gg = *(const float4*)(gz + col);
    float4 bb = *(const float4*)(bz + col);
    float n0 = (a.x - mu) * rstd * gg.x + bb.x;
    float n1 = (a.y - mu) * rstd * gg.y + bb.y;
    float n2 = (a.z - mu) * rstd * gg.z + bb.z;
    float n3 = (a.w - mu) * rstd * gg.w + bb.w;
    float keep = 0.0f;
    #pragma unroll
    for (int h = 0; h < NH_; h++) {
        float4 w = *(const float4*)(&wsT[h * CZ_ + col]);
        float part = n0 * w.x + n1 * w.y + n2 * w.z + n3 * w.w;
        #pragma unroll
        for (int o = 16; o > 0; o >>= 1)
            part += __shfl_xor_sync(0xffffffffu, part, o);
        if (lane == h) keep = part;
    }
    if (lane < NH_) g_zb[(size_t)lane * R_ * R_ + p] = keep;
}

// ---------------- kernel 2b: weight transpose + tf32 round ----------------
__global__ __launch_bounds__(256) void wtrans_kernel(const float* __restrict__ wq,
                                                     const float* __restrict__ wk,
                                                     const float* __restrict__ wv,
                                                     const float* __restrict__ wg,
                                                     const float* __restrict__ wo) {
    __shared__ float t[32][33];
    int mat = blockIdx.z;
    const float* W = (mat == 0) ? wq : (mat == 1) ? wk : (mat == 2) ? wv : (mat == 3) ? wg : wo;
    float* D = (mat < 4) ? (g_wT + (size_t)mat * HC_ * CM_) : g_woT;
    int bx = blockIdx.x, by = blockIdx.y;
    int tx = threadIdx.x & 31, ty8 = threadIdx.x >> 5;
    #pragma unroll
    for (int r = 0; r < 32; r += 8)
        t[ty8 + r][tx] = W[(size_t)(by * 32 + ty8 + r) * 256 + bx * 32 + tx];
    __syncthreads();
    #pragma unroll
    for (int r = 0; r < 32; r += 8)
        D[(size_t)(bx * 32 + ty8 + r) * 256 + by * 32 + tx] = rtf32(t[tx][ty8 + r]);
}

// ---------------- warp-mma tf32 mainloop, cp.async + ldmatrix ----------------
// dynamic smem: 2 stages x (A[128*36] + B[128*36]) = 18432 floats
static __device__ __forceinline__ void stage_cp(float* dA, const float* sA,
                                                float* dB, const float* sB) {
    #pragma unroll
    for (int j = 0; j < 16; j += 4) {
        CPA16(sptr(dA + j), sA + j);
        CPA16(sptr(dB + j), sB + j);
    }
}
static __device__ __forceinline__ void wm_mainloop(const float* __restrict__ Arow0,
                                                   const float* __restrict__ Brow0,
                                                   float* sm, float acc[4][4][4]) {
    int tid = threadIdx.x;
    int wid = tid >> 5, lane = tid & 31;
    int wm = (wid >> 2) * 64, wn = (wid & 3) * 32;
    int lrow = tid >> 1, lk = (tid & 1) * 16;
    const float* Ag = Arow0 + (size_t)lrow * 256 + lk;
    const float* Bg = Brow0 + (size_t)lrow * 256 + lk;
    float* dA0 = sm + lrow * 36 + lk;
    float* dB0 = sm + 4608 + lrow * 36 + lk;

    // ldmatrix lane addresses (bytes, shared space)
    uint32_t base = sptr(sm);
    int r15 = lane & 15, hi4 = (lane >> 4) * 4;
    uint32_t aAddr[4];
    #pragma unroll
    for (int mi = 0; mi < 4; mi++)
        aAddr[mi] = base + (uint32_t)(((wm + mi * 16 + r15) * 36 + hi4) * 4);
    int brow = (lane & 7) + ((lane >> 4) << 3);
    int bcol = ((lane >> 3) & 1) * 4;
    uint32_t bAddr[2];
    #pragma unroll
    for (int p = 0; p < 2; p++)
        bAddr[p] = base + (uint32_t)((4608 + (wn + p * 16 + brow) * 36 + bcol) * 4);

    stage_cp(dA0, Ag, dB0, Bg);
    CPA_COMMIT();
    #pragma unroll 1
    for (int kc = 0; kc < 8; kc++) {
        if (kc < 7) {
            int st = (kc + 1) & 1;
            stage_cp(dA0 + st * 9216, Ag + (kc + 1) * 32, dB0 + st * 9216, Bg + (kc + 1) * 32);
            CPA_COMMIT();
            CPA_WAIT1();
        } else {
            CPA_WAIT0();
        }
        __syncthreads();
        uint32_t soff = (uint32_t)((kc & 1) * 9216 * 4);
        #pragma unroll
        for (int kk = 0; kk < 32; kk += 8) {
            uint32_t ko = soff + (uint32_t)(kk * 4);
            uint32_t af[4][4], bf[2][4];
            LDSM4(af[0][0], af[0][1], af[0][2], af[0][3], aAddr[0] + ko);
            LDSM4(af[1][0], af[1][1], af[1][2], af[1][3], aAddr[1] + ko);
            LDSM4(af[2][0], af[2][1], af[2][2], af[2][3], aAddr[2] + ko);
            LDSM4(af[3][0], af[3][1], af[3][2], af[3][3], aAddr[3] + ko);
            LDSM4(bf[0][0], bf[0][1], bf[0][2], bf[0][3], bAddr[0] + ko);
            LDSM4(bf[1][0], bf[1][1], bf[1][2], bf[1][3], bAddr[1] + ko);
            #pragma unroll
            for (int mi = 0; mi < 4; mi++)
                #pragma unroll
                for (int ni = 0; ni < 4; ni++)
                    mma16n8k8(acc[mi][ni], af[mi], &bf[ni >> 1][(ni & 1) * 2]);
        }
        __syncthreads();
    }
}

// ---------------- kernel 3: projections via warp-mma ----------------
__global__ __launch_bounds__(256, 2) void proj_w(const float* __restrict__ bg) {
    extern __shared__ float smd[];
    float acc[4][4][4];
    #pragma unroll
    for (int a = 0; a < 4; a++)
        #pragma unroll
        for (int b = 0; b < 4; b++)
            #pragma unroll
            for (int c = 0; c < 4; c++) acc[a][b][c] = 0.0f;

    int m0 = blockIdx.x * 128, by = blockIdx.y;
    wm_mainloop(g_mln + (size_t)m0 * 256, g_wT + (size_t)(by * 128) * 256, smd, acc);

    int tid = threadIdx.x, wid = tid >> 5, lane = tid & 31;
    int g = lane >> 2, t = lane & 3;
    int wm = (wid >> 2) * 64, wn = (wid & 3) * 32;
    int mat = by >> 1;
    float* dst = (mat == 0) ? g_q : (mat == 1) ? g_k : (mat == 2) ? g_v : g_g;
    const float qs = 0.17677669529663687f;
    #pragma unroll
    for (int mi = 0; mi < 4; mi++) {
        #pragma unroll
        for (int half = 0; half < 2; half++) {
            int m = m0 + wm + mi * 16 + g + half * 8;
            int s = m >> 8, rr = m & 255;
            #pragma unroll
            for (int ni = 0; ni < 4; ni++) {
                int n = (by & 1) * 128 + wn + ni * 8 + 2 * t;
                int h = n >> 5, c = n & 31;
                float v0 = acc[mi][ni][half * 2 + 0];
                float v1 = acc[mi][ni][half * 2 + 1];
                if (mat == 0) { v0 *= qs; v1 *= qs; }
                else if (mat == 3) {
                    v0 = 1.0f / (1.0f + __expf(-(v0 + bg[n])));
                    v1 = 1.0f / (1.0f + __expf(-(v1 + bg[n + 1])));
                }
                *(float2*)(dst + (((size_t)(s * NH_ + h) * R_ + rr) * CH_ + c)) =
                    make_float2(v0, v1);
            }
        }
    }
}

// ---------------- kernel 4: fused attention, f32x2 register-tiled ----------------
// block per (s,h). thread(ty 0..31, tx 0..7): 8 q rows (4 packed pairs), 4-key / 4-c slices.
__global__ __launch_bounds__(256, 2) void attn2(const float* __restrict__ mask) {
    extern __shared__ float sm[];
    float* Qt = sm;                // [32][256]  Qt[c][q]
    float* Kt = sm + 8192;         // [32][36]   Kt[c][k]
    float* Vs = sm + 9344;         // [32][36]   Vs[k][c]
    float* Ps = sm + 10496;        // [32][260]  Ps[k][q]
    float* mb = sm + 18816;        // [256]

    int sh = blockIdx.x, s = sh >> 3, h = sh & 7;
    int tid = threadIdx.x;
    int ty = tid >> 3, tx = tid & 7;
    int q0 = ty * 8, c0 = tx * 4;

    const float* qg = g_q + (size_t)sh * R_ * CH_;
    const float* kg = g_k + (size_t)sh * R_ * CH_;
    const float* vg = g_v + (size_t)sh * R_ * CH_;

    {   // transpose Q[q][c] -> Qt[c][q]
        const float4* qp = (const float4*)(qg + (size_t)tid * CH_);
        #pragma unroll
        for (int j = 0; j < 8; j++) {
            float4 v = qp[j];
            Qt[(j * 4 + 0) * 256 + tid] = v.x;
            Qt[(j * 4 + 1) * 256 + tid] = v.y;
            Qt[(j * 4 + 2) * 256 + tid] = v.z;
            Qt[(j * 4 + 3) * 256 + tid] = v.w;
        }
    }
    mb[tid] = 1e9f * (mask[s * R_ + tid] - 1.0f);

    float m_[8], l_[8];
    u64 O2[4][4];                 // O2[ip][j] = (O[2ip][j], O[2ip+1][j])
    #pragma unroll
    for (int i = 0; i < 8; i++) { m_[i] = -1e30f; l_[i] = 0.0f; }
    #pragma unroll
    for (int ip = 0; ip < 4; ip++)
        #pragma unroll
        for (int j = 0; j < 4; j++) O2[ip][j] = 0ull;

    const float* zrow = g_zb + (size_t)h * R_ * R_;

    #pragma unroll 1
    for (int k0 = 0; k0 < R_; k0 += 32) {
        __syncthreads();
        {   // stage K (transpose to Kt[c][k]) and V (direct Vs[k][c])
            int k = tid >> 3, c4 = (tid & 7) * 4;
            float4 kv = *(const float4*)(kg + (size_t)(k0 + k) * CH_ + c4);
            Kt[(c4 + 0) * 36 + k] = kv.x;
            Kt[(c4 + 1) * 36 + k] = kv.y;
            Kt[(c4 + 2) * 36 + k] = kv.z;
            Kt[(c4 + 3) * 36 + k] = kv.w;
            float4 vv = *(const float4*)(vg + (size_t)(k0 + k) * CH_ + c4);
            *(float4*)(Vs + k * 36 + c4) = vv;
        }
        __syncthreads();

        // QK^T: pq[ip][j] = packed logits for q-pair ip, key slot j
        u64 pq[4][4];
        #pragma unroll
        for (int ip = 0; ip < 4; ip++)
            #pragma unroll
            for (int j = 0; j < 4; j++) pq[ip][j] = 0ull;
        #pragma unroll 8
        for (int c = 0; c < 32; c++) {
            float4 kb = *(const float4*)(Kt + c * 36 + tx * 4);
            u64 kd[4];
            PACK2(kd[0], kb.x, kb.x); PACK2(kd[1], kb.y, kb.y);
            PACK2(kd[2], kb.z, kb.z); PACK2(kd[3], kb.w, kb.w);
            ulonglong2 qa = *(const ulonglong2*)(Qt + c * 256 + q0);
            ulonglong2 qb = *(const ulonglong2*)(Qt + c * 256 + q0 + 4);
            u64 qp_[4] = {qa.x, qa.y, qb.x, qb.y};
            #pragma unroll
            for (int ip = 0; ip < 4; ip++) {
                FMA2(pq[ip][0], qp_[ip], kd[0]);
                FMA2(pq[ip][1], qp_[ip], kd[1]);
                FMA2(pq[ip][2], qp_[ip], kd[2]);
                FMA2(pq[ip][3], qp_[ip], kd[3]);
            }
        }

        float4 mbv = *(const float4*)(mb + k0 + tx * 4);
        #pragma unroll
        for (int ip = 0; ip < 4; ip++) {
            int ia = 2 * ip, ib = 2 * ip + 1;
            float pa[4], pb[4];
            #pragma unroll
            for (int j = 0; j < 4; j++) UNPACK2(pa[j], pb[j], pq[ip][j]);
            float4 za = *(const float4*)(zrow + (size_t)(q0 + ia) * R_ + k0 + tx * 4);
            float4 zb = *(const float4*)(zrow + (size_t)(q0 + ib) * R_ + k0 + tx * 4);
            pa[0] += mbv.x + za.x; pa[1] += mbv.y + za.y;
            pa[2] += mbv.z + za.z; pa[3] += mbv.w + za.w;
            pb[0] += mbv.x + zb.x; pb[1] += mbv.y + zb.y;
            pb[2] += mbv.z + zb.z; pb[3] += mbv.w + zb.w;
            // row ia
            float ta = fmaxf(fmaxf(pa[0], pa[1]), fmaxf(pa[2], pa[3]));
            ta = fmaxf(ta, __shfl_xor_sync(0xffffffffu, ta, 1));
            ta = fmaxf(ta, __shfl_xor_sync(0xffffffffu, ta, 2));
            ta = fmaxf(ta, __shfl_xor_sync(0xffffffffu, ta, 4));
            float nma = fmaxf(m_[ia], ta);
            float ca = __expf(m_[ia] - nma);
            m_[ia] = nma; l_[ia] *= ca;
            // row ib
            float tb = fmaxf(fmaxf(pb[0], pb[1]), fmaxf(pb[2], pb[3]));
            tb = fmaxf(tb, __shfl_xor_sync(0xffffffffu, tb, 1));
            tb = fmaxf(tb, __shfl_xor_sync(0xffffffffu, tb, 2));
            tb = fmaxf(tb, __shfl_xor_sync(0xffffffffu, tb, 4));
            float nmb = fmaxf(m_[ib], tb);
            float cb = __expf(m_[ib] - nmb);
            m_[ib] = nmb; l_[ib] *= cb;
            // rescale packed output accumulators
            u64 c2; PACK2(c2, ca, cb);
            MUL2I(O2[ip][0], c2); MUL2I(O2[ip][1], c2);
            MUL2I(O2[ip][2], c2); MUL2I(O2[ip][3], c2);
            // exp + paired Ps stores
            #pragma unroll
            for (int j = 0; j < 4; j++) {
                float ea = __expf(pa[j] - nma);
                float eb = __expf(pb[j] - nmb);
                l_[ia] += ea; l_[ib] += eb;
                *(float2*)(Ps + (tx * 4 + j) * 260 + q0 + 2 * ip) = make_float2(ea, eb);
            }
        }
        __syncthreads();

        // AV: O2[ip][j] += P(q-pair) * V[k][c0+j]
        #pragma unroll 8
        for (int kk = 0; kk < 32; kk++) {
            ulonglong2 a0 = *(const ulonglong2*)(Ps + kk * 260 + q0);
            ulonglong2 a1 = *(const ulonglong2*)(Ps + kk * 260 + q0 + 4);
            u64 aq[4] = {a0.x, a0.y, a1.x, a1.y};
            float4 vb = *(const float4*)(Vs + kk * 36 + c0);
            u64 vd[4];
            PACK2(vd[0], vb.x, vb.x); PACK2(vd[1], vb.y, vb.y);
            PACK2(vd[2], vb.z, vb.z); PACK2(vd[3], vb.w, vb.w);
            #pragma unroll
            for (int ip = 0; ip < 4; ip++) {
                FMA2(O2[ip][0], aq[ip], vd[0]);
                FMA2(O2[ip][1], aq[ip], vd[1]);
                FMA2(O2[ip][2], aq[ip], vd[2]);
                FMA2(O2[ip][3], aq[ip], vd[3]);
            }
        }
    }

    float inv[8];
    #pragma unroll
    for (int i = 0; i < 8; i++) {
        float lf = l_[i];
        lf += __shfl_xor_sync(0xffffffffu, lf, 1);
        lf += __shfl_xor_sync(0xffffffffu, lf, 2);
        lf += __shfl_xor_sync(0xffffffffu, lf, 4);
        inv[i] = 1.0f / lf;
    }
    const float* gg = g_g + (size_t)sh * R_ * CH_;
    #pragma unroll
    for (int ip = 0; ip < 4; ip++) {
        float Oa[4], Ob[4];
        #pragma unroll
        for (int j = 0; j < 4; j++) UNPACK2(Oa[j], Ob[j], O2[ip][j]);
        #pragma unroll
        for (int half = 0; half < 2; half++) {
            int i = 2 * ip + half;
            const float* Ov = half ? Ob : Oa;
            int q = q0 + i;
            float4 gv = *(const float4*)(gg + (size_t)q * CH_ + c0);
            float4 o;
            o.x = rtf32(Ov[0] * inv[i] * gv.x);
            o.y = rtf32(Ov[1] * inv[i] * gv.y);
            o.z = rtf32(Ov[2] * inv[i] * gv.z);
            o.w = rtf32(Ov[3] * inv[i] * gv.w);
            *(float4*)(g_og + (size_t)(s * R_ + q) * HC_ + h * CH_ + c0) = o;
        }
    }
}

// ---------------- kernel 5: output GEMM via warp-mma ----------------
__global__ __launch_bounds__(256, 2) void out_w(const float* __restrict__ bo,
                                                float* __restrict__ out) {
    extern __shared__ float smd[];
    float acc[4][4][4];
    #pragma unroll
    for (int a = 0; a < 4; a++)
        #pragma unroll
        for (int b = 0; b < 4; b++)
            #pragma unroll
            for (int c = 0; c < 4; c++) acc[a][b][c] = 0.0f;

    int m0 = blockIdx.x * 128, n0 = blockIdx.y * 128;
    wm_mainloop(g_og + (size_t)m0 * 256, g_woT + (size_t)n0 * 256, smd, acc);

    int tid = threadIdx.x, wid = tid >> 5, lane = tid & 31;
    int g = lane >> 2, t = lane & 3;
    int wm = (wid >> 2) * 64, wn = (wid & 3) * 32;
    #pragma unroll
    for (int mi = 0; mi < 4; mi++) {
        #pragma unroll
        for (int half = 0; half < 2; half++) {
            int m = m0 + wm + mi * 16 + g + half * 8;
            #pragma unroll
            for (int ni = 0; ni < 4; ni++) {
                int n = n0 + wn + ni * 8 + 2 * t;
                float v0 = acc[mi][ni][half * 2 + 0] + bo[n];
                float v1 = acc[mi][ni][half * 2 + 1] + bo[n + 1];
                *(float2*)(out + (size_t)m * CM_ + n) = make_float2(v0, v1);
            }
        }
    }
}

// ---------------- launch ----------------
extern "C" void kernel_launch(void* const* d_in, const int* in_sizes, int n_in,
                              void* d_out, int out_size) {
    (void)in_sizes; (void)n_in; (void)out_size;
    const float* m      = (const float*)d_in[0];
    const float* z      = (const float*)d_in[1];
    const float* mask   = (const float*)d_in[2];
    const float* ln_m_g = (const float*)d_in[3];
    const float* ln_m_b = (const float*)d_in[4];
    const float* ln_z_g = (const float*)d_in[5];
    const float* ln_z_b = (const float*)d_in[6];
    const float* w_z    = (const float*)d_in[7];
    const float* wq     = (const float*)d_in[8];
    const float* wk     = (const float*)d_in[9];
    const float* wv     = (const float*)d_in[10];
    const float* wg     = (const float*)d_in[11];
    const float* bg     = (const float*)d_in[12];
    const float* wo     = (const float*)d_in[13];
    const float* bo     = (const float*)d_in[14];
    float* out = (float*)d_out;

    const int gemm_smem = 73728;  // 2 stages x (A+B) x 128x36 floats
    cudaFuncSetAttribute(proj_w, cudaFuncAttributeMaxDynamicSharedMemorySize, gemm_smem);
    cudaFuncSetAttribute(out_w,  cudaFuncAttributeMaxDynamicSharedMemorySize, gemm_smem);
    const int attn_smem = 19072 * (int)sizeof(float);
    cudaFuncSetAttribute(attn2, cudaFuncAttributeMaxDynamicSharedMemorySize, attn_smem);

    ln_m_kernel<<<MTOT / 8, 256>>>(m, ln_m_g, ln_m_b);
    zbias_kernel<<<R_ * R_ / 8, 256>>>(z, ln_z_g, ln_z_b, w_z);
    wtrans_kernel<<<dim3(8, 8, 5), 256>>>(wq, wk, wv, wg, wo);
    proj_w<<<dim3(MTOT / 128, 8), 256, gemm_smem>>>(bg);
    attn2<<<S_ * NH_, 256, attn_smem>>>(mask);
    out_w<<<dim3(MTOT / 128, 2), 256, gemm_smem>>>(bo, out);
}

// round 12
// speedup vs baseline: 2.1475x; 1.2009x over previous
#include <cuda_runtime.h>
#include <cuda_fp16.h>
#include <math.h>
#include <stdint.h>

#define S_   128
#define R_   256
#define CM_  256
#define CZ_  128
#define NH_  8
#define CH_  32
#define HC_  256
#define MTOT (S_*R_)

typedef unsigned long long u64;

// ---------------- scratch ----------------
__device__ __half g_mlnh[MTOT*CM_];          // LN(m), fp16   [m][k]
__device__ float  g_q[NH_*S_*R_*CH_];        // [s*8+h][r][c] fp32
__device__ float  g_k[NH_*S_*R_*CH_];
__device__ float  g_v[NH_*S_*R_*CH_];
__device__ float  g_g[NH_*S_*R_*CH_];
__device__ __half g_ogh[MTOT*HC_];           // (o*g) fp16    [m][hc]
__device__ float  g_zb[NH_*R_*R_];           // pair bias [h][q][k]
__device__ __half g_wTh[4*HC_*CM_];          // [mat*256+n][k] fp16
__device__ __half g_woTh[CM_*HC_];           // [n][k] fp16

static __device__ __forceinline__ void mma_h(float* d, const uint32_t* a, const uint32_t* b) {
    asm volatile("mma.sync.aligned.m16n8k16.row.col.f32.f16.f16.f32 "
        "{%0,%1,%2,%3}, {%4,%5,%6,%7}, {%8,%9}, {%0,%1,%2,%3};"
        : "+f"(d[0]), "+f"(d[1]), "+f"(d[2]), "+f"(d[3])
        : "r"(a[0]), "r"(a[1]), "r"(a[2]), "r"(a[3]), "r"(b[0]), "r"(b[1]));
}
#define LDSM4(r0, r1, r2, r3, a) \
    asm volatile("ldmatrix.sync.aligned.m8n8.x4.shared.b16 {%0,%1,%2,%3}, [%4];" \
        : "=r"(r0), "=r"(r1), "=r"(r2), "=r"(r3) : "r"(a))
// packed fp32x2 ops (exact IEEE fp32 lanewise)
#define FMA2(d, a, b) asm("fma.rn.f32x2 %0, %1, %2, %0;" : "+l"(d) : "l"(a), "l"(b))
#define MUL2I(d, c)   asm("mul.rn.f32x2 %0, %0, %1;"     : "+l"(d) : "l"(c))
#define PACK2(d, lo, hi)   asm("mov.b64 %0, {%1, %2};" : "=l"(d) : "f"(lo), "f"(hi))
#define UNPACK2(lo, hi, s) asm("mov.b64 {%0, %1}, %2;" : "=f"(lo), "=f"(hi) : "l"(s))
// cp.async 16B
#define CPA16(dst_u32, src) \
    asm volatile("cp.async.ca.shared.global [%0], [%1], 16;" :: "r"(dst_u32), "l"(src))
#define CPA_COMMIT() asm volatile("cp.async.commit_group;" ::: "memory")
#define CPA_WAIT1()  asm volatile("cp.async.wait_group 1;" ::: "memory")
#define CPA_WAIT0()  asm volatile("cp.async.wait_group 0;" ::: "memory")
static __device__ __forceinline__ uint32_t sptr(const void* p) {
    return (uint32_t)__cvta_generic_to_shared(p);
}

// ---------------- kernel 1: LayerNorm(m) -> fp16 ----------------
__global__ __launch_bounds__(256) void ln_m_kernel(const float* __restrict__ m,
                                                   const float* __restrict__ g,
                                                   const float* __restrict__ b) {
    int warp = threadIdx.x >> 5, lane = threadIdx.x & 31;
    int row = blockIdx.x * 8 + warp;
    const float* x = m + (size_t)row * CM_;
    float4 a = *(const float4*)(x + lane * 4);
    float4 c = *(const float4*)(x + 128 + lane * 4);
    float s  = a.x + a.y + a.z + a.w + c.x + c.y + c.z + c.w;
    float ss = a.x*a.x + a.y*a.y + a.z*a.z + a.w*a.w
             + c.x*c.x + c.y*c.y + c.z*c.z + c.w*c.w;
    #pragma unroll
    for (int o = 16; o > 0; o >>= 1) {
        s  += __shfl_xor_sync(0xffffffffu, s,  o);
        ss += __shfl_xor_sync(0xffffffffu, ss, o);
    }
    float mu   = s * (1.0f / CM_);
    float var  = ss * (1.0f / CM_) - mu * mu;
    float rstd = rsqrtf(var + 1e-5f);
    __half2* yh = (__half2*)(g_mlnh + (size_t)row * CM_);
    {
        float4 gg = *(const float4*)(g + lane * 4);
        float4 bb = *(const float4*)(b + lane * 4);
        yh[lane * 2 + 0] = __floats2half2_rn((a.x - mu) * rstd * gg.x + bb.x,
                                             (a.y - mu) * rstd * gg.y + bb.y);
        yh[lane * 2 + 1] = __floats2half2_rn((a.z - mu) * rstd * gg.z + bb.z,
                                             (a.w - mu) * rstd * gg.w + bb.w);
    }
    {
        float4 gg = *(const float4*)(g + 128 + lane * 4);
        float4 bb = *(const float4*)(b + 128 + lane * 4);
        yh[64 + lane * 2 + 0] = __floats2half2_rn((c.x - mu) * rstd * gg.x + bb.x,
                                                  (c.y - mu) * rstd * gg.y + bb.y);
        yh[64 + lane * 2 + 1] = __floats2half2_rn((c.z - mu) * rstd * gg.z + bb.z,
                                                  (c.w - mu) * rstd * gg.w + bb.w);
    }
}

// ---------------- kernel 2: pair bias ----------------
__global__ __launch_bounds__(256) void zbias_kernel(const float* __restrict__ z,
                                                    const float* __restrict__ gz,
                                                    const float* __restrict__ bz,
                                                    const float* __restrict__ wz) {
    __shared__ float wsT[NH_ * CZ_];
    int tid = threadIdx.x;
    for (int i = tid; i < NH_ * CZ_; i += 256) {
        int h = i / CZ_, e = i % CZ_;
        wsT[i] = wz[e * NH_ + h];
    }
    __syncthreads();
    int warp = tid >> 5, lane = tid & 31;
    int p = blockIdx.x * 8 + warp;
    const float* x = z + (size_t)p * CZ_;
    float4 a = *(const float4*)(x + lane * 4);
    float s  = a.x + a.y + a.z + a.w;
    float ss = a.x*a.x + a.y*a.y + a.z*a.z + a.w*a.w;
    #pragma unroll
    for (int o = 16; o > 0; o >>= 1) {
        s  += __shfl_xor_sync(0xffffffffu, s,  o);
        ss += __shfl_xor_sync(0xffffffffu, ss, o);
    }
    float mu   = s * (1.0f / CZ_);
    float var  = ss * (1.0f / CZ_) - mu * mu;
    float rstd = rsqrtf(var + 1e-5f);
    int col = lane * 4;
    float4 gg = *(const float4*)(gz + col);
    float4 bb = *(const float4*)(bz + col);
    float n0 = (a.x - mu) * rstd * gg.x + bb.x;
    float n1 = (a.y - mu) * rstd * gg.y + bb.y;
    float n2 = (a.z - mu) * rstd * gg.z + bb.z;
    float n3 = (a.w - mu) * rstd * gg.w + bb.w;
    float keep = 0.0f;
    #pragma unroll
    for (int h = 0; h < NH_; h++) {
        float4 w = *(const float4*)(&wsT[h * CZ_ + col]);
        float part = n0 * w.x + n1 * w.y + n2 * w.z + n3 * w.w;
        #pragma unroll
        for (int o = 16; o > 0; o >>= 1)
            part += __shfl_xor_sync(0xffffffffu, part, o);
        if (lane == h) keep = part;
    }
    if (lane < NH_) g_zb[(size_t)lane * R_ * R_ + p] = keep;
}

// ---------------- kernel 2b: weight transpose -> fp16 ----------------
__global__ __launch_bounds__(256) void wtrans_kernel(const float* __restrict__ wq,
                                                     const float* __restrict__ wk,
                                                     const float* __restrict__ wv,
                                                     const float* __restrict__ wg,
                                                     const float* __restrict__ wo) {
    __shared__ float t[32][33];
    int mat = blockIdx.z;
    const float* W = (mat == 0) ? wq : (mat == 1) ? wk : (mat == 2) ? wv : (mat == 3) ? wg : wo;
    __half* D = (mat < 4) ? (g_wTh + (size_t)mat * HC_ * CM_) : g_woTh;
    int bx = blockIdx.x, by = blockIdx.y;
    int tx = threadIdx.x & 31, ty8 = threadIdx.x >> 5;
    #pragma unroll
    for (int r = 0; r < 32; r += 8)
        t[ty8 + r][tx] = W[(size_t)(by * 32 + ty8 + r) * 256 + bx * 32 + tx];
    __syncthreads();
    #pragma unroll
    for (int r = 0; r < 32; r += 8)
        D[(size_t)(bx * 32 + ty8 + r) * 256 + by * 32 + tx] = __float2half_rn(t[tx][ty8 + r]);
}

// ---------------- fp16 warp-mma mainloop (128x128 tile, K=256, k-chunks of 32) ----------------
// dynamic smem: 2 stages x (A[128x40] + B[128x40]) halves = 40960 bytes
static __device__ __forceinline__ void stage_cp_h(__half* dA, const __half* sA,
                                                  __half* dB, const __half* sB) {
    CPA16(sptr(dA),     sA);
    CPA16(sptr(dA + 8), sA + 8);
    CPA16(sptr(dB),     sB);
    CPA16(sptr(dB + 8), sB + 8);
}
static __device__ __forceinline__ void wm_mainloop_h(const __half* __restrict__ Arow0,
                                                     const __half* __restrict__ Brow0,
                                                     __half* sm, float acc[4][4][4]) {
    int tid = threadIdx.x;
    int wid = tid >> 5, lane = tid & 31;
    int wm = (wid >> 2) * 64, wn = (wid & 3) * 32;
    int lrow = tid >> 1, lk = (tid & 1) * 16;
    const __half* Ag = Arow0 + (size_t)lrow * 256 + lk;
    const __half* Bg = Brow0 + (size_t)lrow * 256 + lk;
    __half* dA0 = sm + lrow * 40 + lk;
    __half* dB0 = sm + 5120 + lrow * 40 + lk;

    uint32_t base = sptr(sm);
    int r15 = lane & 15, khi = (lane >> 4) * 8;        // halfs
    uint32_t aAddr[4];
    #pragma unroll
    for (int mi = 0; mi < 4; mi++)
        aAddr[mi] = base + (uint32_t)(((wm + mi * 16 + r15) * 40 + khi) * 2);
    int brow = (lane & 7) + ((lane >> 4) << 3);
    int bk = ((lane >> 3) & 1) * 8;                    // halfs
    uint32_t bAddr[2];
    #pragma unroll
    for (int p = 0; p < 2; p++)
        bAddr[p] = base + (uint32_t)((5120 + (wn + p * 16 + brow) * 40 + bk) * 2);

    stage_cp_h(dA0, Ag, dB0, Bg);
    CPA_COMMIT();
    #pragma unroll 1
    for (int kc = 0; kc < 8; kc++) {
        if (kc < 7) {
            int st = (kc + 1) & 1;
            stage_cp_h(dA0 + st * 10240, Ag + (kc + 1) * 32,
                       dB0 + st * 10240, Bg + (kc + 1) * 32);
            CPA_COMMIT();
            CPA_WAIT1();
        } else {
            CPA_WAIT0();
        }
        __syncthreads();
        uint32_t soff = (uint32_t)((kc & 1) * 10240 * 2);
        #pragma unroll
        for (int kk = 0; kk < 2; kk++) {
            uint32_t ko = soff + (uint32_t)(kk * 32);   // 16 halfs = 32 bytes
            uint32_t af[4][4], bf[2][4];
            LDSM4(af[0][0], af[0][1], af[0][2], af[0][3], aAddr[0] + ko);
            LDSM4(af[1][0], af[1][1], af[1][2], af[1][3], aAddr[1] + ko);
            LDSM4(af[2][0], af[2][1], af[2][2], af[2][3], aAddr[2] + ko);
            LDSM4(af[3][0], af[3][1], af[3][2], af[3][3], aAddr[3] + ko);
            LDSM4(bf[0][0], bf[0][1], bf[0][2], bf[0][3], bAddr[0] + ko);
            LDSM4(bf[1][0], bf[1][1], bf[1][2], bf[1][3], bAddr[1] + ko);
            #pragma unroll
            for (int mi = 0; mi < 4; mi++)
                #pragma unroll
                for (int ni = 0; ni < 4; ni++)
                    mma_h(acc[mi][ni], af[mi], &bf[ni >> 1][(ni & 1) * 2]);
        }
        __syncthreads();
    }
}

// ---------------- kernel 3: projections via fp16 warp-mma ----------------
__global__ __launch_bounds__(256, 2) void proj_w(const float* __restrict__ bg) {
    extern __shared__ __half smh[];
    float acc[4][4][4];
    #pragma unroll
    for (int a = 0; a < 4; a++)
        #pragma unroll
        for (int b = 0; b < 4; b++)
            #pragma unroll
            for (int c = 0; c < 4; c++) acc[a][b][c] = 0.0f;

    int m0 = blockIdx.x * 128, by = blockIdx.y;
    wm_mainloop_h(g_mlnh + (size_t)m0 * 256, g_wTh + (size_t)(by * 128) * 256, smh, acc);

    int tid = threadIdx.x, wid = tid >> 5, lane = tid & 31;
    int g = lane >> 2, t = lane & 3;
    int wm = (wid >> 2) * 64, wn = (wid & 3) * 32;
    int mat = by >> 1;
    float* dst = (mat == 0) ? g_q : (mat == 1) ? g_k : (mat == 2) ? g_v : g_g;
    const float qs = 0.17677669529663687f;
    #pragma unroll
    for (int mi = 0; mi < 4; mi++) {
        #pragma unroll
        for (int half = 0; half < 2; half++) {
            int m = m0 + wm + mi * 16 + g + half * 8;
            int s = m >> 8, rr = m & 255;
            #pragma unroll
            for (int ni = 0; ni < 4; ni++) {
                int n = (by & 1) * 128 + wn + ni * 8 + 2 * t;
                int h = n >> 5, c = n & 31;
                float v0 = acc[mi][ni][half * 2 + 0];
                float v1 = acc[mi][ni][half * 2 + 1];
                if (mat == 0) { v0 *= qs; v1 *= qs; }
                else if (mat == 3) {
                    v0 = 1.0f / (1.0f + __expf(-(v0 + bg[n])));
                    v1 = 1.0f / (1.0f + __expf(-(v1 + bg[n + 1])));
                }
                *(float2*)(dst + (((size_t)(s * NH_ + h) * R_ + rr) * CH_ + c)) =
                    make_float2(v0, v1);
            }
        }
    }
}

// ---------------- kernel 4: fused attention, f32x2 register-tiled (exact) ----------------
// block per (s,h). thread(ty 0..31, tx 0..7): 8 q rows (4 packed pairs), 4-key / 4-c slices.
__global__ __launch_bounds__(256, 2) void attn2(const float* __restrict__ mask) {
    extern __shared__ float sm[];
    float* Qt = sm;                // [32][256]  Qt[c][q]
    float* Kt = sm + 8192;         // [32][36]   Kt[c][k]
    float* Vs = sm + 9344;         // [32][36]   Vs[k][c]
    float* Ps = sm + 10496;        // [32][260]  Ps[k][q]
    float* mb = sm + 18816;        // [256]

    int sh = blockIdx.x, s = sh >> 3, h = sh & 7;
    int tid = threadIdx.x;
    int ty = tid >> 3, tx = tid & 7;
    int q0 = ty * 8, c0 = tx * 4;

    const float* qg = g_q + (size_t)sh * R_ * CH_;
    const float* kg = g_k + (size_t)sh * R_ * CH_;
    const float* vg = g_v + (size_t)sh * R_ * CH_;

    {   // transpose Q[q][c] -> Qt[c][q]
        const float4* qp = (const float4*)(qg + (size_t)tid * CH_);
        #pragma unroll
        for (int j = 0; j < 8; j++) {
            float4 v = qp[j];
            Qt[(j * 4 + 0) * 256 + tid] = v.x;
            Qt[(j * 4 + 1) * 256 + tid] = v.y;
            Qt[(j * 4 + 2) * 256 + tid] = v.z;
            Qt[(j * 4 + 3) * 256 + tid] = v.w;
        }
    }
    mb[tid] = 1e9f * (mask[s * R_ + tid] - 1.0f);

    float m_[8], l_[8];
    u64 O2[4][4];                 // O2[ip][j] = (O[2ip][j], O[2ip+1][j])
    #pragma unroll
    for (int i = 0; i < 8; i++) { m_[i] = -1e30f; l_[i] = 0.0f; }
    #pragma unroll
    for (int ip = 0; ip < 4; ip++)
        #pragma unroll
        for (int j = 0; j < 4; j++) O2[ip][j] = 0ull;

    const float* zrow = g_zb + (size_t)h * R_ * R_;

    #pragma unroll 1
    for (int k0 = 0; k0 < R_; k0 += 32) {
        __syncthreads();
        {   // stage K tile [c][kk] and V tile [kk][c]
            int k = tid >> 3, c4 = (tid & 7) * 4;
            float4 kv = *(const float4*)(kg + (size_t)(k0 + k) * CH_ + c4);
            Kt[(c4 + 0) * 36 + k] = kv.x;
            Kt[(c4 + 1) * 36 + k] = kv.y;
            Kt[(c4 + 2) * 36 + k] = kv.z;
            Kt[(c4 + 3) * 36 + k] = kv.w;
            float4 vv = *(const float4*)(vg + (size_t)(k0 + k) * CH_ + c4);
            *(float4*)(Vs + k * 36 + c4) = vv;
        }
        __syncthreads();

        // QK^T: pq[ip][j] = packed logits for q-pair ip, key slot j
        u64 pq[4][4];
        #pragma unroll
        for (int ip = 0; ip < 4; ip++)
            #pragma unroll
            for (int j = 0; j < 4; j++) pq[ip][j] = 0ull;
        #pragma unroll 8
        for (int c = 0; c < 32; c++) {
            float4 kb = *(const float4*)(Kt + c * 36 + tx * 4);
            u64 kd[4];
            PACK2(kd[0], kb.x, kb.x); PACK2(kd[1], kb.y, kb.y);
            PACK2(kd[2], kb.z, kb.z); PACK2(kd[3], kb.w, kb.w);
            ulonglong2 qa = *(const ulonglong2*)(Qt + c * 256 + q0);
            ulonglong2 qb = *(const ulonglong2*)(Qt + c * 256 + q0 + 4);
            u64 qp_[4] = {qa.x, qa.y, qb.x, qb.y};
            #pragma unroll
            for (int ip = 0; ip < 4; ip++) {
                FMA2(pq[ip][0], qp_[ip], kd[0]);
                FMA2(pq[ip][1], qp_[ip], kd[1]);
                FMA2(pq[ip][2], qp_[ip], kd[2]);
                FMA2(pq[ip][3], qp_[ip], kd[3]);
            }
        }

        float4 mbv = *(const float4*)(mb + k0 + tx * 4);
        #pragma unroll
        for (int ip = 0; ip < 4; ip++) {
            int ia = 2 * ip, ib = 2 * ip + 1;
            float pa[4], pb[4];
            #pragma unroll
            for (int j = 0; j < 4; j++) UNPACK2(pa[j], pb[j], pq[ip][j]);
            float4 za = *(const float4*)(zrow + (size_t)(q0 + ia) * R_ + k0 + tx * 4);
            float4 zb = *(const float4*)(zrow + (size_t)(q0 + ib) * R_ + k0 + tx * 4);
            pa[0] += mbv.x + za.x; pa[1] += mbv.y + za.y;
            pa[2] += mbv.z + za.z; pa[3] += mbv.w + za.w;
            pb[0] += mbv.x + zb.x; pb[1] += mbv.y + zb.y;
            pb[2] += mbv.z + zb.z; pb[3] += mbv.w + zb.w;
            // row ia
            float ta = fmaxf(fmaxf(pa[0], pa[1]), fmaxf(pa[2], pa[3]));
            ta = fmaxf(ta, __shfl_xor_sync(0xffffffffu, ta, 1));
            ta = fmaxf(ta, __shfl_xor_sync(0xffffffffu, ta, 2));
            ta = fmaxf(ta, __shfl_xor_sync(0xffffffffu, ta, 4));
            float nma = fmaxf(m_[ia], ta);
            float ca = __expf(m_[ia] - nma);
            m_[ia] = nma; l_[ia] *= ca;
            // row ib
            float tb = fmaxf(fmaxf(pb[0], pb[1]), fmaxf(pb[2], pb[3]));
            tb = fmaxf(tb, __shfl_xor_sync(0xffffffffu, tb, 1));
            tb = fmaxf(tb, __shfl_xor_sync(0xffffffffu, tb, 2));
            tb = fmaxf(tb, __shfl_xor_sync(0xffffffffu, tb, 4));
            float nmb = fmaxf(m_[ib], tb);
            float cb = __expf(m_[ib] - nmb);
            m_[ib] = nmb; l_[ib] *= cb;
            // rescale packed output accumulators
            u64 c2; PACK2(c2, ca, cb);
            MUL2I(O2[ip][0], c2); MUL2I(O2[ip][1], c2);
            MUL2I(O2[ip][2], c2); MUL2I(O2[ip][3], c2);
            // exp + paired Ps stores
            #pragma unroll
            for (int j = 0; j < 4; j++) {
                float ea = __expf(pa[j] - nma);
                float eb = __expf(pb[j] - nmb);
                l_[ia] += ea; l_[ib] += eb;
                *(float2*)(Ps + (tx * 4 + j) * 260 + q0 + 2 * ip) = make_float2(ea, eb);
            }
        }
        __syncthreads();

        // AV: O2[ip][j] += P(q-pair) * V[k][c0+j]
        #pragma unroll 8
        for (int kk = 0; kk < 32; kk++) {
            ulonglong2 a0 = *(const ulonglong2*)(Ps + kk * 260 + q0);
            ulonglong2 a1 = *(const ulonglong2*)(Ps + kk * 260 + q0 + 4);
            u64 aq[4] = {a0.x, a0.y, a1.x, a1.y};
            float4 vb = *(const float4*)(Vs + kk * 36 + c0);
            u64 vd[4];
            PACK2(vd[0], vb.x, vb.x); PACK2(vd[1], vb.y, vb.y);
            PACK2(vd[2], vb.z, vb.z); PACK2(vd[3], vb.w, vb.w);
            #pragma unroll
            for (int ip = 0; ip < 4; ip++) {
                FMA2(O2[ip][0], aq[ip], vd[0]);
                FMA2(O2[ip][1], aq[ip], vd[1]);
                FMA2(O2[ip][2], aq[ip], vd[2]);
                FMA2(O2[ip][3], aq[ip], vd[3]);
            }
        }
    }

    float inv[8];
    #pragma unroll
    for (int i = 0; i < 8; i++) {
        float lf = l_[i];
        lf += __shfl_xor_sync(0xffffffffu, lf, 1);
        lf += __shfl_xor_sync(0xffffffffu, lf, 2);
        lf += __shfl_xor_sync(0xffffffffu, lf, 4);
        inv[i] = 1.0f / lf;
    }
    const float* gg = g_g + (size_t)sh * R_ * CH_;
    #pragma unroll
    for (int ip = 0; ip < 4; ip++) {
        float Oa[4], Ob[4];
        #pragma unroll
        for (int j = 0; j < 4; j++) UNPACK2(Oa[j], Ob[j], O2[ip][j]);
        #pragma unroll
        for (int half = 0; half < 2; half++) {
            int i = 2 * ip + half;
            const float* Ov = half ? Ob : Oa;
            int q = q0 + i;
            float4 gv = *(const float4*)(gg + (size_t)q * CH_ + c0);
            __half2* op = (__half2*)(g_ogh + (size_t)(s * R_ + q) * HC_ + h * CH_ + c0);
            op[0] = __floats2half2_rn(Ov[0] * inv[i] * gv.x, Ov[1] * inv[i] * gv.y);
            op[1] = __floats2half2_rn(Ov[2] * inv[i] * gv.z, Ov[3] * inv[i] * gv.w);
        }
    }
}

// ---------------- kernel 5: output GEMM via fp16 warp-mma ----------------
__global__ __launch_bounds__(256, 2) void out_w(const float* __restrict__ bo,
                                                float* __restrict__ out) {
    extern __shared__ __half smh[];
    float acc[4][4][4];
    #pragma unroll
    for (int a = 0; a < 4; a++)
        #pragma unroll
        for (int b = 0; b < 4; b++)
            #pragma unroll
            for (int c = 0; c < 4; c++) acc[a][b][c] = 0.0f;

    int m0 = blockIdx.x * 128, n0 = blockIdx.y * 128;
    wm_mainloop_h(g_ogh + (size_t)m0 * 256, g_woTh + (size_t)n0 * 256, smh, acc);

    int tid = threadIdx.x, wid = tid >> 5, lane = tid & 31;
    int g = lane >> 2, t = lane & 3;
    int wm = (wid >> 2) * 64, wn = (wid & 3) * 32;
    #pragma unroll
    for (int mi = 0; mi < 4; mi++) {
        #pragma unroll
        for (int half = 0; half < 2; half++) {
            int m = m0 + wm + mi * 16 + g + half * 8;
            #pragma unroll
            for (int ni = 0; ni < 4; ni++) {
                int n = n0 + wn + ni * 8 + 2 * t;
                float v0 = acc[mi][ni][half * 2 + 0] + bo[n];
                float v1 = acc[mi][ni][half * 2 + 1] + bo[n + 1];
                *(float2*)(out + (size_t)m * CM_ + n) = make_float2(v0, v1);
            }
        }
    }
}

// ---------------- launch ----------------
extern "C" void kernel_launch(void* const* d_in, const int* in_sizes, int n_in,
                              void* d_out, int out_size) {
    (void)in_sizes; (void)n_in; (void)out_size;
    const float* m      = (const float*)d_in[0];
    const float* z      = (const float*)d_in[1];
    const float* mask   = (const float*)d_in[2];
    const float* ln_m_g = (const float*)d_in[3];
    const float* ln_m_b = (const float*)d_in[4];
    const float* ln_z_g = (const float*)d_in[5];
    const float* ln_z_b = (const float*)d_in[6];
    const float* w_z    = (const float*)d_in[7];
    const float* wq     = (const float*)d_in[8];
    const float* wk     = (const float*)d_in[9];
    const float* wv     = (const float*)d_in[10];
    const float* wg     = (const float*)d_in[11];
    const float* bg     = (const float*)d_in[12];
    const float* wo     = (const float*)d_in[13];
    const float* bo     = (const float*)d_in[14];
    float* out = (float*)d_out;

    const int gemm_smem = 40960;  // 2 stages x (A+B) x 128x40 halfs
    cudaFuncSetAttribute(proj_w, cudaFuncAttributeMaxDynamicSharedMemorySize, gemm_smem);
    cudaFuncSetAttribute(out_w,  cudaFuncAttributeMaxDynamicSharedMemorySize, gemm_smem);
    const int attn_smem = 19072 * (int)sizeof(float);
    cudaFuncSetAttribute(attn2, cudaFuncAttributeMaxDynamicSharedMemorySize, attn_smem);

    ln_m_kernel<<<MTOT / 8, 256>>>(m, ln_m_g, ln_m_b);
    zbias_kernel<<<R_ * R_ / 8, 256>>>(z, ln_z_g, ln_z_b, w_z);
    wtrans_kernel<<<dim3(8, 8, 5), 256>>>(wq, wk, wv, wg, wo);
    proj_w<<<dim3(MTOT / 128, 8), 256, gemm_smem>>>(bg);
    attn2<<<S_ * NH_, 256, attn_smem>>>(mask);
    out_w<<<dim3(MTOT / 128, 2), 256, gemm_smem>>>(bo, out);
}